// round 10
// baseline (speedup 1.0000x reference)
#include <cuda_runtime.h>
#include <cstdint>

#define NN 30000
#define DMAXX 16

// ---------------- scratch (static device arrays; no cudaMalloc) -------------
__device__ __align__(16) float d_G1[(size_t)NN * 512];
__device__ __align__(16) float d_G2[(size_t)NN * 1024];
__device__ __align__(16) float d_H1a[(size_t)NN * 128];   // H double buffers (perm order, tf32-rounded)
__device__ __align__(16) float d_H1b[(size_t)NN * 128];
__device__ __align__(16) float d_C1p[(size_t)NN * 128];
__device__ __align__(16) float d_H2a[(size_t)NN * 256];
__device__ __align__(16) float d_H2b[(size_t)NN * 256];
__device__ __align__(16) float d_C2p[(size_t)NN * 256];
__device__ __align__(16) float d_M1[(size_t)NN * 128];
__device__ __align__(16) float d_M2[(size_t)NN * 256];
__device__ __align__(16) float d_X1[(size_t)NN * 256];
__device__ __align__(16) float d_Fr[(size_t)NN * 128];
__device__ __align__(16) float d_Wih1r[512 * 128];
__device__ __align__(16) float d_Whh1r[512 * 128];
__device__ __align__(16) float d_Wself1r[256 * 128];
__device__ __align__(16) float d_Wneigh1r[256 * 128];
__device__ __align__(16) float d_Wih2r[1024 * 256];
__device__ __align__(16) float d_Whh2r[1024 * 256];
__device__ __align__(16) float d_Wself2r[64 * 256];
__device__ __align__(16) float d_Wneigh2r[64 * 256];
__device__ int d_perm[NN];
__device__ int d_hist[17];
__device__ int d_suffix[18];
__device__ int d_offset[17];

// ---------------- tf32 round helpers ----------------------------------------
__device__ __forceinline__ uint32_t f2tf32(float x) {
    uint32_t y;
    asm("cvt.rna.tf32.f32 %0, %1;" : "=r"(y) : "f"(x));
    return y;
}
__device__ __forceinline__ float rtf(float x) { return __uint_as_float(f2tf32(x)); }

__global__ void k_round4(const float* __restrict__ in, float* __restrict__ out, int n4) {
    int i = blockIdx.x * blockDim.x + threadIdx.x;
    if (i < n4) {
        float4 v = ((const float4*)in)[i];
        v.x = rtf(v.x); v.y = rtf(v.y); v.z = rtf(v.z); v.w = rtf(v.w);
        ((float4*)out)[i] = v;
    }
}

// ---------------- degree counting sort (descending) -------------------------
__global__ void k_hist_zero() { if (threadIdx.x < 17) d_hist[threadIdx.x] = 0; }
__global__ void k_hist(const int* __restrict__ deg) {
    int n = blockIdx.x * blockDim.x + threadIdx.x;
    if (n < NN) atomicAdd(&d_hist[deg[n]], 1);
}
__global__ void k_scan() {
    d_suffix[17] = 0;
    for (int dd = 16; dd >= 1; --dd) d_suffix[dd] = d_suffix[dd + 1] + d_hist[dd];
    d_suffix[0] = d_suffix[1];
    for (int dd = 1; dd <= 16; ++dd) d_offset[dd] = d_suffix[dd + 1];
}
__global__ void k_scatter(const int* __restrict__ deg) {
    int n = blockIdx.x * blockDim.x + threadIdx.x;
    if (n < NN) {
        int pos = atomicAdd(&d_offset[deg[n]], 1);
        d_perm[pos] = n;
    }
}

// ---------------- mma + cp.async helpers -------------------------------------
__device__ __forceinline__ void mma_tf32(float& c0, float& c1, float& c2, float& c3,
                                         uint32_t a0, uint32_t a1, uint32_t a2, uint32_t a3,
                                         uint32_t b0, uint32_t b1) {
    asm volatile(
        "mma.sync.aligned.m16n8k8.row.col.f32.tf32.tf32.f32 "
        "{%0,%1,%2,%3}, {%4,%5,%6,%7}, {%8,%9}, {%0,%1,%2,%3};"
        : "+f"(c0), "+f"(c1), "+f"(c2), "+f"(c3)
        : "r"(a0), "r"(a1), "r"(a2), "r"(a3), "r"(b0), "r"(b1));
}
__device__ __forceinline__ void cp_async16(uint32_t dst_smem, const void* src, int src_bytes) {
    asm volatile("cp.async.cg.shared.global [%0], [%1], 16, %2;"
                 :: "r"(dst_smem), "l"(src), "r"(src_bytes));
}
__device__ __forceinline__ void cp_commit() { asm volatile("cp.async.commit_group;"); }
__device__ __forceinline__ void cp_wait0() { asm volatile("cp.async.wait_group 0;"); }

__device__ __forceinline__ float tanh_f(float x) {
    float y;
    asm("tanh.approx.f32 %0, %1;" : "=f"(y) : "f"(x));
    return y;
}
__device__ __forceinline__ float sigm_(float x) {
    return fmaf(tanh_f(0.5f * x), 0.5f, 0.5f);
}

// ---------------- plain tf32 GEMM (round-9 proven core) ----------------------
template<int BM, int BN, int WARPS_M, int WARPS_N, bool ACC, bool RELU, bool ROUND>
__global__ __launch_bounds__(256, 2)
void tgemm_nt(const float* __restrict__ A, const float* __restrict__ W,
              const float* __restrict__ bias0, const float* __restrict__ bias1,
              float* __restrict__ C, int M, int Nn, int K,
              const int* rowsDev) {
    constexpr int BK = 32;
    constexpr int LDS_ = BK + 4;
    constexpr int WM = BM / WARPS_M;
    constexpr int WN = BN / WARPS_N;
    constexpr int MT = WM / 16;
    constexpr int NTT = WN / 8;
    constexpr int NTHR = WARPS_M * WARPS_N * 32;
    constexpr int AIT = BM * (BK / 4) / NTHR;
    constexpr int BIT = BN * (BK / 4) / NTHR;
    constexpr int ASTRIDE = BM * LDS_;
    constexpr int BSTRIDE = BN * LDS_;

    extern __shared__ uint32_t dynsmem[];
    uint32_t* AsBase = dynsmem;
    uint32_t* BsBase = dynsmem + 2 * ASTRIDE;
    const uint32_t sbase = (uint32_t)__cvta_generic_to_shared(dynsmem);
    const uint32_t sbaseB = sbase + 2 * ASTRIDE * 4;

    int rows = rowsDev ? *rowsDev : M;
    int rowBase = blockIdx.y * BM;
    if (rowBase >= rows) return;
    int colBase = blockIdx.x * BN;

    int tid = threadIdx.x;
    int wid = tid >> 5, lane = tid & 31;
    int wm = wid / WARPS_N, wn = wid % WARPS_N;
    int grp = lane >> 2, tg = lane & 3;

    float acc[MT][NTT][4];
#pragma unroll
    for (int i = 0; i < MT; i++)
#pragma unroll
        for (int j = 0; j < NTT; j++) {
            acc[i][j][0] = 0.f; acc[i][j][1] = 0.f; acc[i][j][2] = 0.f; acc[i][j][3] = 0.f;
        }

    const int ar = tid / (BK / 4);
    const int ac4 = (tid % (BK / 4)) * 4;
    constexpr int ARSTEP = NTHR / (BK / 4);

    auto issue_tile = [&](int k0, int stg) {
#pragma unroll
        for (int u = 0; u < AIT; u++) {
            int r = ar + u * ARSTEP;
            int gr = rowBase + r;
            uint32_t dst = sbase + (uint32_t)(stg * ASTRIDE + r * LDS_ + ac4) * 4;
            cp_async16(dst, &A[(size_t)gr * K + k0 + ac4], (gr < rows) ? 16 : 0);
        }
#pragma unroll
        for (int u = 0; u < BIT; u++) {
            int r = ar + u * ARSTEP;
            uint32_t dst = sbaseB + (uint32_t)(stg * BSTRIDE + r * LDS_ + ac4) * 4;
            cp_async16(dst, &W[(size_t)(colBase + r) * K + k0 + ac4], 16);
        }
        cp_commit();
    };

    issue_tile(0, 0);

    int stage = 0;
    for (int k0 = 0; k0 < K; k0 += BK, stage ^= 1) {
        cp_wait0();
        __syncthreads();
        int kn = k0 + BK;
        if (kn < K) issue_tile(kn, stage ^ 1);

        uint32_t* As = AsBase + stage * ASTRIDE;
        uint32_t* Bs = BsBase + stage * BSTRIDE;
#pragma unroll
        for (int kk = 0; kk < BK; kk += 8) {
            uint32_t af[MT][4];
#pragma unroll
            for (int i = 0; i < MT; i++) {
                int r0 = wm * WM + i * 16 + grp;
                int c = kk + tg;
                af[i][0] = As[r0 * LDS_ + c];
                af[i][1] = As[(r0 + 8) * LDS_ + c];
                af[i][2] = As[r0 * LDS_ + c + 4];
                af[i][3] = As[(r0 + 8) * LDS_ + c + 4];
            }
            uint32_t bf[NTT][2];
#pragma unroll
            for (int j = 0; j < NTT; j++) {
                int n0 = wn * WN + j * 8 + grp;
                bf[j][0] = Bs[n0 * LDS_ + kk + tg];
                bf[j][1] = Bs[n0 * LDS_ + kk + tg + 4];
            }
#pragma unroll
            for (int i = 0; i < MT; i++)
#pragma unroll
                for (int j = 0; j < NTT; j++)
                    mma_tf32(acc[i][j][0], acc[i][j][1], acc[i][j][2], acc[i][j][3],
                             af[i][0], af[i][1], af[i][2], af[i][3], bf[j][0], bf[j][1]);
        }
        __syncthreads();
    }

#pragma unroll
    for (int i = 0; i < MT; i++) {
#pragma unroll
        for (int j = 0; j < NTT; j++) {
            int gc = colBase + wn * WN + j * 8 + 2 * tg;
            float b0v = 0.f, b1v = 0.f;
            if (bias0) { b0v += bias0[gc]; b1v += bias0[gc + 1]; }
            if (bias1) { b0v += bias1[gc]; b1v += bias1[gc + 1]; }
            int gr0 = rowBase + wm * WM + i * 16 + grp;
            if (gr0 < rows) {
                float v0 = acc[i][j][0] + b0v, v1 = acc[i][j][1] + b1v;
                float* p = &C[(size_t)gr0 * Nn + gc];
                if (ACC) { v0 += p[0]; v1 += p[1]; }
                if (RELU) { v0 = fmaxf(v0, 0.f); v1 = fmaxf(v1, 0.f); }
                if (ROUND) { v0 = rtf(v0); v1 = rtf(v1); }
                *(float2*)p = make_float2(v0, v1);
            }
            int gr1 = gr0 + 8;
            if (gr1 < rows) {
                float v0 = acc[i][j][2] + b0v, v1 = acc[i][j][3] + b1v;
                float* p = &C[(size_t)gr1 * Nn + gc];
                if (ACC) { v0 += p[0]; v1 += p[1]; }
                if (RELU) { v0 = fmaxf(v0, 0.f); v1 = fmaxf(v1, 0.f); }
                if (ROUND) { v0 = rtf(v0); v1 = rtf(v1); }
                *(float2*)p = make_float2(v0, v1);
            }
        }
    }
}

// ---------------- fused recurrent LSTM step (register-resident epilogue) -----
// Gate-interleaved B mapping: CTA col n = wn*32 + j*8 + c  ->  W row = j*H + ub + wn*8 + c
// => thread (wn,tg) fragment j=0..3 holds gates i,f,g,o of units ub+wn*8+2tg{,+1}.
template<int H>
__global__ __launch_bounds__(256, 2)
void lstm_fused(const float* __restrict__ Hin, const float* __restrict__ W,
                const float* __restrict__ G, float* __restrict__ Hout,
                float* __restrict__ Cst, const int* __restrict__ nbr, int t) {
    constexpr int BM = 128, BN = 128, BK = 32, LDS_ = 36;
    constexpr int MT = 4, NTT = 4;
    constexpr int NTHR = 256;
    constexpr int AIT = BM * (BK / 4) / NTHR;
    constexpr int BIT = BN * (BK / 4) / NTHR;
    constexpr int ASTRIDE = BM * LDS_;
    constexpr int BSTRIDE = BN * LDS_;
    const int K = H;

    extern __shared__ uint32_t dynsmem[];
    uint32_t* AsBase = dynsmem;
    uint32_t* BsBase = dynsmem + 2 * ASTRIDE;
    const uint32_t sbase = (uint32_t)__cvta_generic_to_shared(dynsmem);
    const uint32_t sbaseB = sbase + 2 * ASTRIDE * 4;

    int rows = d_suffix[t + 1];
    int rowBase = blockIdx.y * BM;
    if (rowBase >= rows) return;
    const int ub = blockIdx.x * 32;    // hidden-unit base for this CTA

    int tid = threadIdx.x;
    int wid = tid >> 5, lane = tid & 31;
    int wm = wid >> 2, wn = wid & 3;
    int grp = lane >> 2, tg = lane & 3;

    float acc[MT][NTT][4];
#pragma unroll
    for (int i = 0; i < MT; i++)
#pragma unroll
        for (int j = 0; j < NTT; j++) {
            acc[i][j][0] = 0.f; acc[i][j][1] = 0.f; acc[i][j][2] = 0.f; acc[i][j][3] = 0.f;
        }

    const int ar = tid / (BK / 4);
    const int ac4 = (tid % (BK / 4)) * 4;
    constexpr int ARSTEP = NTHR / (BK / 4);

    auto issue_tile = [&](int k0, int stg) {
#pragma unroll
        for (int u = 0; u < AIT; u++) {
            int r = ar + u * ARSTEP;
            int gr = rowBase + r;
            uint32_t dst = sbase + (uint32_t)(stg * ASTRIDE + r * LDS_ + ac4) * 4;
            cp_async16(dst, &Hin[(size_t)gr * K + k0 + ac4], (gr < rows) ? 16 : 0);
        }
#pragma unroll
        for (int u = 0; u < BIT; u++) {
            int r = ar + u * ARSTEP;
            // gate-interleaved W row mapping
            int wrow = ((r >> 3) & 3) * H + ub + (r >> 5) * 8 + (r & 7);
            uint32_t dst = sbaseB + (uint32_t)(stg * BSTRIDE + r * LDS_ + ac4) * 4;
            cp_async16(dst, &W[(size_t)wrow * K + k0 + ac4], 16);
        }
        cp_commit();
    };

    issue_tile(0, 0);

    int stage = 0;
    for (int k0 = 0; k0 < K; k0 += BK, stage ^= 1) {
        cp_wait0();
        __syncthreads();
        int kn = k0 + BK;
        if (kn < K) issue_tile(kn, stage ^ 1);

        uint32_t* As = AsBase + stage * ASTRIDE;
        uint32_t* Bs = BsBase + stage * BSTRIDE;
#pragma unroll
        for (int kk = 0; kk < BK; kk += 8) {
            uint32_t af[MT][4];
#pragma unroll
            for (int i = 0; i < MT; i++) {
                int r0 = wm * 64 + i * 16 + grp;
                int c = kk + tg;
                af[i][0] = As[r0 * LDS_ + c];
                af[i][1] = As[(r0 + 8) * LDS_ + c];
                af[i][2] = As[r0 * LDS_ + c + 4];
                af[i][3] = As[(r0 + 8) * LDS_ + c + 4];
            }
            uint32_t bf[NTT][2];
#pragma unroll
            for (int j = 0; j < NTT; j++) {
                int n0 = wn * 32 + j * 8 + grp;
                bf[j][0] = Bs[n0 * LDS_ + kk + tg];
                bf[j][1] = Bs[n0 * LDS_ + kk + tg + 4];
            }
#pragma unroll
            for (int i = 0; i < MT; i++)
#pragma unroll
                for (int j = 0; j < NTT; j++)
                    mma_tf32(acc[i][j][0], acc[i][j][1], acc[i][j][2], acc[i][j][3],
                             af[i][0], af[i][1], af[i][2], af[i][3], bf[j][0], bf[j][1]);
        }
        __syncthreads();
    }

    // register-resident LSTM epilogue: acc[i][j][q] = gate j, row (q>>1), unit q&1
    const int u0 = ub + wn * 8 + 2 * tg;
#pragma unroll
    for (int i = 0; i < MT; i++) {
#pragma unroll
        for (int half = 0; half < 2; half++) {
            int pr = rowBase + wm * 64 + i * 16 + grp + half * 8;
            if (pr < rows) {
                int node = d_perm[pr];
                int nr = nbr[node * DMAXX + t];
                const float* g = &G[(size_t)nr * 4 * H];
                size_t coff = (size_t)pr * H + u0;
#pragma unroll
                for (int d = 0; d < 2; d++) {
                    int q = half * 2 + d;
                    int u = u0 + d;
                    float gi = acc[i][0][q] + g[u];
                    float gf = acc[i][1][q] + g[H + u];
                    float gg = acc[i][2][q] + g[2 * H + u];
                    float go = acc[i][3][q] + g[3 * H + u];
                    float c = Cst[coff + d];
                    c = sigm_(gf) * c + sigm_(gi) * tanh_f(gg);
                    Cst[coff + d] = c;
                    Hout[coff + d] = rtf(sigm_(go) * tanh_f(c));
                }
            }
        }
    }
}

// t = 0 step: gates come straight from G. C full precision; H stored rounded.
template<int H>
__global__ void lstm_step0(const float* __restrict__ G, const int* __restrict__ nbr,
                           float* __restrict__ Hp, float* __restrict__ Cp) {
    constexpr int TPN = H / 4;
    int cnt = d_suffix[1];
    int idx = blockIdx.x * blockDim.x + threadIdx.x;
    int p = idx / TPN;
    if (p >= cnt) return;
    int lane = idx % TPN;
    int node = d_perm[p];
    int nr = nbr[node * DMAXX];
    const float4* gx = (const float4*)&G[(size_t)nr * 4 * H];
    float4 xi = gx[lane], xg = gx[2 * TPN + lane], xo = gx[3 * TPN + lane];
    float4 c, h;
    c.x = sigm_(xi.x) * tanh_f(xg.x); h.x = rtf(sigm_(xo.x) * tanh_f(c.x));
    c.y = sigm_(xi.y) * tanh_f(xg.y); h.y = rtf(sigm_(xo.y) * tanh_f(c.y));
    c.z = sigm_(xi.z) * tanh_f(xg.z); h.z = rtf(sigm_(xo.z) * tanh_f(c.z));
    c.w = sigm_(xi.w) * tanh_f(xg.w); h.w = rtf(sigm_(xo.w) * tanh_f(c.w));
    ((float4*)&Cp[(size_t)p * H])[lane] = c;
    ((float4*)&Hp[(size_t)p * H])[lane] = h;
}

// scatter final hidden (buffer by deg parity: odd deg -> Hb, even -> Ha)
__global__ void k_scatter_h1(const int* __restrict__ deg) {
    int idx = blockIdx.x * blockDim.x + threadIdx.x;
    if (idx >= NN * 32) return;
    int p = idx >> 5, lane = idx & 31;
    int node = d_perm[p];
    const float4* src = (deg[node] & 1) ? (const float4*)d_H1b : (const float4*)d_H1a;
    ((float4*)d_M1)[node * 32 + lane] = src[p * 32 + lane];
}
__global__ void k_scatter_h2(const int* __restrict__ deg) {
    int idx = blockIdx.x * blockDim.x + threadIdx.x;
    if (idx >= NN * 64) return;
    int p = idx >> 6, lane = idx & 63;
    int node = d_perm[p];
    const float4* src = (deg[node] & 1) ? (const float4*)d_H2b : (const float4*)d_H2a;
    ((float4*)d_M2)[node * 64 + lane] = src[p * 64 + lane];
}

// ---------------- launch -----------------------------------------------------
extern "C" void kernel_launch(void* const* d_in, const int* in_sizes, int n_in,
                              void* d_out, int out_size) {
    const float* feat    = (const float*)d_in[0];
    const int*   nbr     = (const int*)  d_in[1];
    const int*   deg     = (const int*)  d_in[2];
    const float* Wih1    = (const float*)d_in[3];
    const float* Whh1    = (const float*)d_in[4];
    const float* bih1    = (const float*)d_in[5];
    const float* bhh1    = (const float*)d_in[6];
    const float* Wself1  = (const float*)d_in[7];
    const float* Wneigh1 = (const float*)d_in[8];
    const float* b1      = (const float*)d_in[9];
    const float* Wih2    = (const float*)d_in[10];
    const float* Whh2    = (const float*)d_in[11];
    const float* bih2    = (const float*)d_in[12];
    const float* bhh2    = (const float*)d_in[13];
    const float* Wself2  = (const float*)d_in[14];
    const float* Wneigh2 = (const float*)d_in[15];
    const float* b2      = (const float*)d_in[16];
    float* out = (float*)d_out;

    float *pG1, *pG2, *pH1a, *pH1b, *pC1, *pH2a, *pH2b, *pC2, *pM1, *pM2, *pX1, *pFr;
    float *pWih1r, *pWhh1r, *pWself1r, *pWneigh1r, *pWih2r, *pWhh2r, *pWself2r, *pWneigh2r;
    cudaGetSymbolAddress((void**)&pG1, d_G1);
    cudaGetSymbolAddress((void**)&pG2, d_G2);
    cudaGetSymbolAddress((void**)&pH1a, d_H1a);
    cudaGetSymbolAddress((void**)&pH1b, d_H1b);
    cudaGetSymbolAddress((void**)&pC1, d_C1p);
    cudaGetSymbolAddress((void**)&pH2a, d_H2a);
    cudaGetSymbolAddress((void**)&pH2b, d_H2b);
    cudaGetSymbolAddress((void**)&pC2, d_C2p);
    cudaGetSymbolAddress((void**)&pM1, d_M1);
    cudaGetSymbolAddress((void**)&pM2, d_M2);
    cudaGetSymbolAddress((void**)&pX1, d_X1);
    cudaGetSymbolAddress((void**)&pFr, d_Fr);
    cudaGetSymbolAddress((void**)&pWih1r, d_Wih1r);
    cudaGetSymbolAddress((void**)&pWhh1r, d_Whh1r);
    cudaGetSymbolAddress((void**)&pWself1r, d_Wself1r);
    cudaGetSymbolAddress((void**)&pWneigh1r, d_Wneigh1r);
    cudaGetSymbolAddress((void**)&pWih2r, d_Wih2r);
    cudaGetSymbolAddress((void**)&pWhh2r, d_Whh2r);
    cudaGetSymbolAddress((void**)&pWself2r, d_Wself2r);
    cudaGetSymbolAddress((void**)&pWneigh2r, d_Wneigh2r);

    const int SM_BIG = 2 * (128 + 128) * 36 * 4;   // 73728
    const int SM_SMALL = 2 * (128 + 64) * 36 * 4;  // 55296
    cudaFuncSetAttribute((const void*)tgemm_nt<128, 128, 2, 4, false, false, false>,
                         cudaFuncAttributeMaxDynamicSharedMemorySize, SM_BIG);
    cudaFuncSetAttribute((const void*)tgemm_nt<128, 128, 2, 4, true, true, true>,
                         cudaFuncAttributeMaxDynamicSharedMemorySize, SM_BIG);
    cudaFuncSetAttribute((const void*)tgemm_nt<128, 64, 2, 4, false, false, false>,
                         cudaFuncAttributeMaxDynamicSharedMemorySize, SM_SMALL);
    cudaFuncSetAttribute((const void*)tgemm_nt<128, 64, 2, 4, true, false, false>,
                         cudaFuncAttributeMaxDynamicSharedMemorySize, SM_SMALL);
    cudaFuncSetAttribute((const void*)lstm_fused<128>,
                         cudaFuncAttributeMaxDynamicSharedMemorySize, SM_BIG);
    cudaFuncSetAttribute((const void*)lstm_fused<256>,
                         cudaFuncAttributeMaxDynamicSharedMemorySize, SM_BIG);

    const int MB = (NN + 127) / 128;  // 235

    k_round4<<<(NN * 32 + 255) / 256, 256>>>(feat, pFr, NN * 32);
    k_round4<<<(512 * 32 + 255) / 256, 256>>>(Wih1, pWih1r, 512 * 32);
    k_round4<<<(512 * 32 + 255) / 256, 256>>>(Whh1, pWhh1r, 512 * 32);
    k_round4<<<(256 * 32 + 255) / 256, 256>>>(Wself1, pWself1r, 256 * 32);
    k_round4<<<(256 * 32 + 255) / 256, 256>>>(Wneigh1, pWneigh1r, 256 * 32);
    k_round4<<<(1024 * 64 + 255) / 256, 256>>>(Wih2, pWih2r, 1024 * 64);
    k_round4<<<(1024 * 64 + 255) / 256, 256>>>(Whh2, pWhh2r, 1024 * 64);
    k_round4<<<(64 * 64 + 255) / 256, 256>>>(Wself2, pWself2r, 64 * 64);
    k_round4<<<(64 * 64 + 255) / 256, 256>>>(Wneigh2, pWneigh2r, 64 * 64);

    k_hist_zero<<<1, 32>>>();
    k_hist<<<(NN + 255) / 256, 256>>>(deg);
    k_scan<<<1, 1>>>();
    k_scatter<<<(NN + 255) / 256, 256>>>(deg);

    // ---------------- layer 1 ----------------
    tgemm_nt<128, 128, 2, 4, false, false, false><<<dim3(4, MB), 256, SM_BIG>>>(
        pFr, pWih1r, bih1, bhh1, pG1, NN, 512, 128, nullptr);
    lstm_step0<128><<<(NN * 32 + 255) / 256, 256>>>(pG1, nbr, pH1b, pC1);   // t=0 -> Hb
    for (int t = 1; t < DMAXX; t++) {
        const float* hin = (t & 1) ? pH1b : pH1a;
        float* hout = (t & 1) ? pH1a : pH1b;
        lstm_fused<128><<<dim3(4, MB), 256, SM_BIG>>>(hin, pWhh1r, pG1, hout, pC1, nbr, t);
    }
    k_scatter_h1<<<(NN * 32 + 255) / 256, 256>>>(deg);
    tgemm_nt<128, 128, 2, 4, false, false, false><<<dim3(2, MB), 256, SM_BIG>>>(
        pFr, pWself1r, b1, nullptr, pX1, NN, 256, 128, nullptr);
    tgemm_nt<128, 128, 2, 4, true, true, true><<<dim3(2, MB), 256, SM_BIG>>>(
        pM1, pWneigh1r, nullptr, nullptr, pX1, NN, 256, 128, nullptr);

    // ---------------- layer 2 ----------------
    tgemm_nt<128, 128, 2, 4, false, false, false><<<dim3(8, MB), 256, SM_BIG>>>(
        pX1, pWih2r, bih2, bhh2, pG2, NN, 1024, 256, nullptr);
    lstm_step0<256><<<(NN * 64 + 255) / 256, 256>>>(pG2, nbr, pH2b, pC2);   // t=0 -> Hb
    for (int t = 1; t < DMAXX; t++) {
        const float* hin = (t & 1) ? pH2b : pH2a;
        float* hout = (t & 1) ? pH2a : pH2b;
        lstm_fused<256><<<dim3(8, MB), 256, SM_BIG>>>(hin, pWhh2r, pG2, hout, pC2, nbr, t);
    }
    k_scatter_h2<<<(NN * 64 + 255) / 256, 256>>>(deg);
    tgemm_nt<128, 64, 2, 4, false, false, false><<<dim3(1, MB), 256, SM_SMALL>>>(
        pX1, pWself2r, b2, nullptr, out, NN, 64, 256, nullptr);
    tgemm_nt<128, 64, 2, 4, true, false, false><<<dim3(1, MB), 256, SM_SMALL>>>(
        pM2, pWneigh2r, nullptr, nullptr, out, NN, 64, 256, nullptr);
}

// round 11
// speedup vs baseline: 2.0987x; 2.0987x over previous
#include <cuda_runtime.h>
#include <cstdint>

#define NN 30000
#define DMAXX 16

// ---------------- scratch (static device arrays; no cudaMalloc) -------------
__device__ __align__(16) float d_G1[(size_t)NN * 512];
__device__ __align__(16) float d_GB[(size_t)NN * 1024];
__device__ __align__(16) float d_H1p[(size_t)NN * 128];
__device__ __align__(16) float d_C1p[(size_t)NN * 128];
__device__ __align__(16) float d_M1[(size_t)NN * 128];
__device__ __align__(16) float d_X1[(size_t)NN * 256];
__device__ __align__(16) float d_G2[(size_t)NN * 1024];
__device__ __align__(16) float d_H2p[(size_t)NN * 256];
__device__ __align__(16) float d_C2p[(size_t)NN * 256];
__device__ __align__(16) float d_M2[(size_t)NN * 256];
__device__ __align__(16) float d_Fr[(size_t)NN * 128];
__device__ __align__(16) float d_Wih1r[512 * 128];
__device__ __align__(16) float d_Whh1r[512 * 128];
__device__ __align__(16) float d_Wself1r[256 * 128];
__device__ __align__(16) float d_Wneigh1r[256 * 128];
__device__ __align__(16) float d_Wih2r[1024 * 256];
__device__ __align__(16) float d_Whh2r[1024 * 256];
__device__ __align__(16) float d_Wself2r[64 * 256];
__device__ __align__(16) float d_Wneigh2r[64 * 256];
__device__ int d_perm[NN];
__device__ int d_hist[17];
__device__ int d_suffix[18];
__device__ int d_offset[17];

// ---------------- tf32 round helpers ----------------------------------------
__device__ __forceinline__ uint32_t f2tf32(float x) {
    uint32_t y;
    asm("cvt.rna.tf32.f32 %0, %1;" : "=r"(y) : "f"(x));
    return y;
}
__device__ __forceinline__ float rtf(float x) { return __uint_as_float(f2tf32(x)); }

__global__ void k_round4(const float* __restrict__ in, float* __restrict__ out, int n4) {
    int i = blockIdx.x * blockDim.x + threadIdx.x;
    if (i < n4) {
        float4 v = ((const float4*)in)[i];
        v.x = rtf(v.x); v.y = rtf(v.y); v.z = rtf(v.z); v.w = rtf(v.w);
        ((float4*)out)[i] = v;
    }
}

// ---------------- degree counting sort (descending) -------------------------
__global__ void k_hist_zero() { if (threadIdx.x < 17) d_hist[threadIdx.x] = 0; }
__global__ void k_hist(const int* __restrict__ deg) {
    int n = blockIdx.x * blockDim.x + threadIdx.x;
    if (n < NN) atomicAdd(&d_hist[deg[n]], 1);
}
__global__ void k_scan() {
    d_suffix[17] = 0;
    for (int dd = 16; dd >= 1; --dd) d_suffix[dd] = d_suffix[dd + 1] + d_hist[dd];
    d_suffix[0] = d_suffix[1];
    for (int dd = 1; dd <= 16; ++dd) d_offset[dd] = d_suffix[dd + 1];
}
__global__ void k_scatter(const int* __restrict__ deg) {
    int n = blockIdx.x * blockDim.x + threadIdx.x;
    if (n < NN) {
        int pos = atomicAdd(&d_offset[deg[n]], 1);
        d_perm[pos] = n;
    }
}

// ---------------- mma + cp.async helpers -------------------------------------
__device__ __forceinline__ void mma_tf32(float& c0, float& c1, float& c2, float& c3,
                                         uint32_t a0, uint32_t a1, uint32_t a2, uint32_t a3,
                                         uint32_t b0, uint32_t b1) {
    asm volatile(
        "mma.sync.aligned.m16n8k8.row.col.f32.tf32.tf32.f32 "
        "{%0,%1,%2,%3}, {%4,%5,%6,%7}, {%8,%9}, {%0,%1,%2,%3};"
        : "+f"(c0), "+f"(c1), "+f"(c2), "+f"(c3)
        : "r"(a0), "r"(a1), "r"(a2), "r"(a3), "r"(b0), "r"(b1));
}
__device__ __forceinline__ void cp_async16(uint32_t dst_smem, const void* src, int src_bytes) {
    asm volatile("cp.async.cg.shared.global [%0], [%1], 16, %2;"
                 :: "r"(dst_smem), "l"(src), "r"(src_bytes));
}
__device__ __forceinline__ void cp_commit() { asm volatile("cp.async.commit_group;"); }
__device__ __forceinline__ void cp_wait0() { asm volatile("cp.async.wait_group 0;"); }

// ---------------- tf32 GEMM: BK=32, cp.async 2-stage pipeline ----------------
// Inputs pre-rounded to tf32 (rna) in gmem; loads are raw 16B copies.
template<int BM, int BN, int WARPS_M, int WARPS_N, bool ACC, bool RELU, bool ROUND>
__global__ __launch_bounds__(WARPS_M * WARPS_N * 32, 1024 / (WARPS_M * WARPS_N * 64))
void tgemm_nt(const float* __restrict__ A, const float* __restrict__ W,
              const float* __restrict__ bias0, const float* __restrict__ bias1,
              float* __restrict__ C, int M, int Nn, int K,
              const int* rowsDev) {
    constexpr int BK = 32;
    constexpr int LDS_ = BK + 4;
    constexpr int WM = BM / WARPS_M;
    constexpr int WN = BN / WARPS_N;
    constexpr int MT = WM / 16;
    constexpr int NTT = WN / 8;
    constexpr int NTHR = WARPS_M * WARPS_N * 32;
    constexpr int AIT = BM * (BK / 4) / NTHR;
    constexpr int BIT = BN * (BK / 4) / NTHR;
    constexpr int ASTRIDE = BM * LDS_;
    constexpr int BSTRIDE = BN * LDS_;

    extern __shared__ uint32_t dynsmem[];
    uint32_t* AsBase = dynsmem;
    uint32_t* BsBase = dynsmem + 2 * ASTRIDE;
    const uint32_t sbase = (uint32_t)__cvta_generic_to_shared(dynsmem);
    const uint32_t sbaseB = sbase + 2 * ASTRIDE * 4;

    int rows = rowsDev ? *rowsDev : M;
    int rowBase = blockIdx.y * BM;
    if (rowBase >= rows) return;
    int colBase = blockIdx.x * BN;

    int tid = threadIdx.x;
    int wid = tid >> 5, lane = tid & 31;
    int wm = wid / WARPS_N, wn = wid % WARPS_N;
    int grp = lane >> 2, tg = lane & 3;

    float acc[MT][NTT][4];
#pragma unroll
    for (int i = 0; i < MT; i++)
#pragma unroll
        for (int j = 0; j < NTT; j++) {
            acc[i][j][0] = 0.f; acc[i][j][1] = 0.f; acc[i][j][2] = 0.f; acc[i][j][3] = 0.f;
        }

    const int ar = tid / (BK / 4);
    const int ac4 = (tid % (BK / 4)) * 4;
    constexpr int ARSTEP = NTHR / (BK / 4);

    auto issue_tile = [&](int k0, int stg) {
#pragma unroll
        for (int u = 0; u < AIT; u++) {
            int r = ar + u * ARSTEP;
            int gr = rowBase + r;
            uint32_t dst = sbase + (uint32_t)(stg * ASTRIDE + r * LDS_ + ac4) * 4;
            cp_async16(dst, &A[(size_t)gr * K + k0 + ac4], (gr < rows) ? 16 : 0);
        }
#pragma unroll
        for (int u = 0; u < BIT; u++) {
            int r = ar + u * ARSTEP;
            uint32_t dst = sbaseB + (uint32_t)(stg * BSTRIDE + r * LDS_ + ac4) * 4;
            cp_async16(dst, &W[(size_t)(colBase + r) * K + k0 + ac4], 16);
        }
        cp_commit();
    };

    issue_tile(0, 0);

    int stage = 0;
    for (int k0 = 0; k0 < K; k0 += BK, stage ^= 1) {
        cp_wait0();
        __syncthreads();
        int kn = k0 + BK;
        if (kn < K) issue_tile(kn, stage ^ 1);

        uint32_t* As = AsBase + stage * ASTRIDE;
        uint32_t* Bs = BsBase + stage * BSTRIDE;
#pragma unroll
        for (int kk = 0; kk < BK; kk += 8) {
            uint32_t af[MT][4];
#pragma unroll
            for (int i = 0; i < MT; i++) {
                int r0 = wm * WM + i * 16 + grp;
                int c = kk + tg;
                af[i][0] = As[r0 * LDS_ + c];
                af[i][1] = As[(r0 + 8) * LDS_ + c];
                af[i][2] = As[r0 * LDS_ + c + 4];
                af[i][3] = As[(r0 + 8) * LDS_ + c + 4];
            }
            uint32_t bf[NTT][2];
#pragma unroll
            for (int j = 0; j < NTT; j++) {
                int n0 = wn * WN + j * 8 + grp;
                bf[j][0] = Bs[n0 * LDS_ + kk + tg];
                bf[j][1] = Bs[n0 * LDS_ + kk + tg + 4];
            }
#pragma unroll
            for (int i = 0; i < MT; i++)
#pragma unroll
                for (int j = 0; j < NTT; j++)
                    mma_tf32(acc[i][j][0], acc[i][j][1], acc[i][j][2], acc[i][j][3],
                             af[i][0], af[i][1], af[i][2], af[i][3], bf[j][0], bf[j][1]);
        }
        __syncthreads();
    }

#pragma unroll
    for (int i = 0; i < MT; i++) {
#pragma unroll
        for (int j = 0; j < NTT; j++) {
            int gc = colBase + wn * WN + j * 8 + 2 * tg;
            float b0v = 0.f, b1v = 0.f;
            if (bias0) { b0v += bias0[gc]; b1v += bias0[gc + 1]; }
            if (bias1) { b0v += bias1[gc]; b1v += bias1[gc + 1]; }
            int gr0 = rowBase + wm * WM + i * 16 + grp;
            if (gr0 < rows) {
                float v0 = acc[i][j][0] + b0v, v1 = acc[i][j][1] + b1v;
                float* p = &C[(size_t)gr0 * Nn + gc];
                if (ACC) { v0 += p[0]; v1 += p[1]; }
                if (RELU) { v0 = fmaxf(v0, 0.f); v1 = fmaxf(v1, 0.f); }
                if (ROUND) { v0 = rtf(v0); v1 = rtf(v1); }
                *(float2*)p = make_float2(v0, v1);
            }
            int gr1 = gr0 + 8;
            if (gr1 < rows) {
                float v0 = acc[i][j][2] + b0v, v1 = acc[i][j][3] + b1v;
                float* p = &C[(size_t)gr1 * Nn + gc];
                if (ACC) { v0 += p[0]; v1 += p[1]; }
                if (RELU) { v0 = fmaxf(v0, 0.f); v1 = fmaxf(v1, 0.f); }
                if (ROUND) { v0 = rtf(v0); v1 = rtf(v1); }
                *(float2*)p = make_float2(v0, v1);
            }
        }
    }
}

// ---------------- fast activations (hardware MUFU.TANH) ----------------------
__device__ __forceinline__ float tanh_f(float x) {
    float y;
    asm("tanh.approx.f32 %0, %1;" : "=f"(y) : "f"(x));
    return y;
}
__device__ __forceinline__ float sigm_(float x) {
    return fmaf(tanh_f(0.5f * x), 0.5f, 0.5f);
}

// t = 0 step: gates come straight from G. C full precision; H stored rounded.
template<int H>
__global__ void lstm_step0(const float* __restrict__ G, const int* __restrict__ nbr,
                           float* __restrict__ Hp, float* __restrict__ Cp) {
    constexpr int TPN = H / 4;
    int cnt = d_suffix[1];
    int idx = blockIdx.x * blockDim.x + threadIdx.x;
    int p = idx / TPN;
    if (p >= cnt) return;
    int lane = idx % TPN;
    int node = d_perm[p];
    int nr = nbr[node * DMAXX];
    const float4* gx = (const float4*)&G[(size_t)nr * 4 * H];
    float4 xi = gx[lane], xg = gx[2 * TPN + lane], xo = gx[3 * TPN + lane];
    float4 c, h;
    c.x = sigm_(xi.x) * tanh_f(xg.x); h.x = rtf(sigm_(xo.x) * tanh_f(c.x));
    c.y = sigm_(xi.y) * tanh_f(xg.y); h.y = rtf(sigm_(xo.y) * tanh_f(c.y));
    c.z = sigm_(xi.z) * tanh_f(xg.z); h.z = rtf(sigm_(xo.z) * tanh_f(c.z));
    c.w = sigm_(xi.w) * tanh_f(xg.w); h.w = rtf(sigm_(xo.w) * tanh_f(c.w));
    ((float4*)&Cp[(size_t)p * H])[lane] = c;
    ((float4*)&Hp[(size_t)p * H])[lane] = h;
}

// layer 1: H=128; 32 threads/node. H stored rounded, C full precision.
__global__ void lstm_step1(const int* __restrict__ nbr, int t) {
    int cnt = d_suffix[t + 1];
    int idx = blockIdx.x * blockDim.x + threadIdx.x;
    int p = idx >> 5;
    if (p >= cnt) return;
    int lane = idx & 31;
    int node = d_perm[p];
    int nr = nbr[node * DMAXX + t];
    const float4* gb = (const float4*)&d_GB[(size_t)p * 512];
    const float4* gx = (const float4*)&d_G1[(size_t)nr * 512];
    float4 gi = gb[lane],       xi = gx[lane];
    float4 gf = gb[32 + lane],  xf = gx[32 + lane];
    float4 gg = gb[64 + lane],  xg = gx[64 + lane];
    float4 go = gb[96 + lane],  xo = gx[96 + lane];
    float4* cp = (float4*)&d_C1p[(size_t)p * 128];
    float4* hp = (float4*)&d_H1p[(size_t)p * 128];
    float4 c = cp[lane];
    float4 h;
    c.x = sigm_(gf.x + xf.x) * c.x + sigm_(gi.x + xi.x) * tanh_f(gg.x + xg.x); h.x = rtf(sigm_(go.x + xo.x) * tanh_f(c.x));
    c.y = sigm_(gf.y + xf.y) * c.y + sigm_(gi.y + xi.y) * tanh_f(gg.y + xg.y); h.y = rtf(sigm_(go.y + xo.y) * tanh_f(c.y));
    c.z = sigm_(gf.z + xf.z) * c.z + sigm_(gi.z + xi.z) * tanh_f(gg.z + xg.z); h.z = rtf(sigm_(go.z + xo.z) * tanh_f(c.z));
    c.w = sigm_(gf.w + xf.w) * c.w + sigm_(gi.w + xi.w) * tanh_f(gg.w + xg.w); h.w = rtf(sigm_(go.w + xo.w) * tanh_f(c.w));
    cp[lane] = c; hp[lane] = h;
}

// layer 2: H=256; 64 threads/node
__global__ void lstm_step2(const int* __restrict__ nbr, int t) {
    int cnt = d_suffix[t + 1];
    int idx = blockIdx.x * blockDim.x + threadIdx.x;
    int p = idx >> 6;
    if (p >= cnt) return;
    int lane = idx & 63;
    int node = d_perm[p];
    int nr = nbr[node * DMAXX + t];
    const float4* gb = (const float4*)&d_GB[(size_t)p * 1024];
    const float4* gx = (const float4*)&d_G2[(size_t)nr * 1024];
    float4 gi = gb[lane],        xi = gx[lane];
    float4 gf = gb[64 + lane],   xf = gx[64 + lane];
    float4 gg = gb[128 + lane],  xg = gx[128 + lane];
    float4 go = gb[192 + lane],  xo = gx[192 + lane];
    float4* cp = (float4*)&d_C2p[(size_t)p * 256];
    float4* hp = (float4*)&d_H2p[(size_t)p * 256];
    float4 c = cp[lane];
    float4 h;
    c.x = sigm_(gf.x + xf.x) * c.x + sigm_(gi.x + xi.x) * tanh_f(gg.x + xg.x); h.x = rtf(sigm_(go.x + xo.x) * tanh_f(c.x));
    c.y = sigm_(gf.y + xf.y) * c.y + sigm_(gi.y + xi.y) * tanh_f(gg.y + xg.y); h.y = rtf(sigm_(go.y + xo.y) * tanh_f(c.y));
    c.z = sigm_(gf.z + xf.z) * c.z + sigm_(gi.z + xi.z) * tanh_f(gg.z + xg.z); h.z = rtf(sigm_(go.z + xo.z) * tanh_f(c.z));
    c.w = sigm_(gf.w + xf.w) * c.w + sigm_(gi.w + xi.w) * tanh_f(gg.w + xg.w); h.w = rtf(sigm_(go.w + xo.w) * tanh_f(c.w));
    cp[lane] = c; hp[lane] = h;
}

// scatter permuted final hidden state back to natural node order
__global__ void k_scatter_h1() {
    int idx = blockIdx.x * blockDim.x + threadIdx.x;
    if (idx >= NN * 32) return;
    int p = idx >> 5, lane = idx & 31;
    int node = d_perm[p];
    ((float4*)d_M1)[node * 32 + lane] = ((const float4*)d_H1p)[p * 32 + lane];
}
__global__ void k_scatter_h2() {
    int idx = blockIdx.x * blockDim.x + threadIdx.x;
    if (idx >= NN * 64) return;
    int p = idx >> 6, lane = idx & 63;
    int node = d_perm[p];
    ((float4*)d_M2)[node * 64 + lane] = ((const float4*)d_H2p)[p * 64 + lane];
}

// ---------------- launch -----------------------------------------------------
extern "C" void kernel_launch(void* const* d_in, const int* in_sizes, int n_in,
                              void* d_out, int out_size) {
    const float* feat    = (const float*)d_in[0];
    const int*   nbr     = (const int*)  d_in[1];
    const int*   deg     = (const int*)  d_in[2];
    const float* Wih1    = (const float*)d_in[3];
    const float* Whh1    = (const float*)d_in[4];
    const float* bih1    = (const float*)d_in[5];
    const float* bhh1    = (const float*)d_in[6];
    const float* Wself1  = (const float*)d_in[7];
    const float* Wneigh1 = (const float*)d_in[8];
    const float* b1      = (const float*)d_in[9];
    const float* Wih2    = (const float*)d_in[10];
    const float* Whh2    = (const float*)d_in[11];
    const float* bih2    = (const float*)d_in[12];
    const float* bhh2    = (const float*)d_in[13];
    const float* Wself2  = (const float*)d_in[14];
    const float* Wneigh2 = (const float*)d_in[15];
    const float* b2      = (const float*)d_in[16];
    float* out = (float*)d_out;

    float *pG1, *pGB, *pH1, *pC1, *pM1, *pX1, *pG2, *pH2, *pC2, *pM2, *pFr;
    float *pWih1r, *pWhh1r, *pWself1r, *pWneigh1r, *pWih2r, *pWhh2r, *pWself2r, *pWneigh2r;
    int* pSuf;
    cudaGetSymbolAddress((void**)&pG1, d_G1);
    cudaGetSymbolAddress((void**)&pGB, d_GB);
    cudaGetSymbolAddress((void**)&pH1, d_H1p);
    cudaGetSymbolAddress((void**)&pC1, d_C1p);
    cudaGetSymbolAddress((void**)&pM1, d_M1);
    cudaGetSymbolAddress((void**)&pX1, d_X1);
    cudaGetSymbolAddress((void**)&pG2, d_G2);
    cudaGetSymbolAddress((void**)&pH2, d_H2p);
    cudaGetSymbolAddress((void**)&pC2, d_C2p);
    cudaGetSymbolAddress((void**)&pM2, d_M2);
    cudaGetSymbolAddress((void**)&pFr, d_Fr);
    cudaGetSymbolAddress((void**)&pWih1r, d_Wih1r);
    cudaGetSymbolAddress((void**)&pWhh1r, d_Whh1r);
    cudaGetSymbolAddress((void**)&pWself1r, d_Wself1r);
    cudaGetSymbolAddress((void**)&pWneigh1r, d_Wneigh1r);
    cudaGetSymbolAddress((void**)&pWih2r, d_Wih2r);
    cudaGetSymbolAddress((void**)&pWhh2r, d_Whh2r);
    cudaGetSymbolAddress((void**)&pWself2r, d_Wself2r);
    cudaGetSymbolAddress((void**)&pWneigh2r, d_Wneigh2r);
    cudaGetSymbolAddress((void**)&pSuf, d_suffix);

    const int SM_BIG = 2 * (128 + 128) * 36 * 4;    // 73728
    const int SM_BIG2 = 2 * (256 + 128) * 36 * 4;   // 110592
    const int SM_SMALL = 2 * (128 + 64) * 36 * 4;   // 55296
    cudaFuncSetAttribute((const void*)tgemm_nt<128, 128, 2, 4, false, false, false>,
                         cudaFuncAttributeMaxDynamicSharedMemorySize, SM_BIG);
    cudaFuncSetAttribute((const void*)tgemm_nt<256, 128, 4, 4, false, false, false>,
                         cudaFuncAttributeMaxDynamicSharedMemorySize, SM_BIG2);
    cudaFuncSetAttribute((const void*)tgemm_nt<128, 128, 2, 4, true, true, true>,
                         cudaFuncAttributeMaxDynamicSharedMemorySize, SM_BIG);
    cudaFuncSetAttribute((const void*)tgemm_nt<128, 64, 2, 4, false, false, false>,
                         cudaFuncAttributeMaxDynamicSharedMemorySize, SM_SMALL);
    cudaFuncSetAttribute((const void*)tgemm_nt<128, 64, 2, 4, true, false, false>,
                         cudaFuncAttributeMaxDynamicSharedMemorySize, SM_SMALL);

    const int MB = (NN + 127) / 128;   // 235
    const int MB2 = (NN + 255) / 256;  // 118

    k_round4<<<(NN * 32 + 255) / 256, 256>>>(feat, pFr, NN * 32);
    k_round4<<<(512 * 32 + 255) / 256, 256>>>(Wih1, pWih1r, 512 * 32);
    k_round4<<<(512 * 32 + 255) / 256, 256>>>(Whh1, pWhh1r, 512 * 32);
    k_round4<<<(256 * 32 + 255) / 256, 256>>>(Wself1, pWself1r, 256 * 32);
    k_round4<<<(256 * 32 + 255) / 256, 256>>>(Wneigh1, pWneigh1r, 256 * 32);
    k_round4<<<(1024 * 64 + 255) / 256, 256>>>(Wih2, pWih2r, 1024 * 64);
    k_round4<<<(1024 * 64 + 255) / 256, 256>>>(Whh2, pWhh2r, 1024 * 64);
    k_round4<<<(64 * 64 + 255) / 256, 256>>>(Wself2, pWself2r, 64 * 64);
    k_round4<<<(64 * 64 + 255) / 256, 256>>>(Wneigh2, pWneigh2r, 64 * 64);

    k_hist_zero<<<1, 32>>>();
    k_hist<<<(NN + 255) / 256, 256>>>(deg);
    k_scan<<<1, 1>>>();
    k_scatter<<<(NN + 255) / 256, 256>>>(deg);

    // ---------------- layer 1 ----------------
    tgemm_nt<128, 128, 2, 4, false, false, false><<<dim3(4, MB), 256, SM_BIG>>>(
        pFr, pWih1r, bih1, bhh1, pG1, NN, 512, 128, nullptr);
    lstm_step0<128><<<(NN * 32 + 255) / 256, 256>>>(pG1, nbr, pH1, pC1);
    for (int t = 1; t < DMAXX; t++) {
        tgemm_nt<128, 128, 2, 4, false, false, false><<<dim3(4, MB), 256, SM_BIG>>>(
            pH1, pWhh1r, nullptr, nullptr, pGB, NN, 512, 128, pSuf + (t + 1));
        lstm_step1<<<(NN * 32 + 255) / 256, 256>>>(nbr, t);
    }
    k_scatter_h1<<<(NN * 32 + 255) / 256, 256>>>();
    tgemm_nt<128, 128, 2, 4, false, false, false><<<dim3(2, MB), 256, SM_BIG>>>(
        pFr, pWself1r, b1, nullptr, pX1, NN, 256, 128, nullptr);
    tgemm_nt<128, 128, 2, 4, true, true, true><<<dim3(2, MB), 256, SM_BIG>>>(
        pM1, pWneigh1r, nullptr, nullptr, pX1, NN, 256, 128, nullptr);

    // ---------------- layer 2 (BM=256 tiles: halve Whh2/Wih2 L2 streaming) ---
    tgemm_nt<256, 128, 4, 4, false, false, false><<<dim3(8, MB2), 512, SM_BIG2>>>(
        pX1, pWih2r, bih2, bhh2, pG2, NN, 1024, 256, nullptr);
    lstm_step0<256><<<(NN * 64 + 255) / 256, 256>>>(pG2, nbr, pH2, pC2);
    for (int t = 1; t < DMAXX; t++) {
        tgemm_nt<256, 128, 4, 4, false, false, false><<<dim3(8, MB2), 512, SM_BIG2>>>(
            pH2, pWhh2r, nullptr, nullptr, pGB, NN, 1024, 256, pSuf + (t + 1));
        lstm_step2<<<(NN * 64 + 255) / 256, 256>>>(nbr, t);
    }
    k_scatter_h2<<<(NN * 64 + 255) / 256, 256>>>();
    tgemm_nt<128, 64, 2, 4, false, false, false><<<dim3(1, MB), 256, SM_SMALL>>>(
        pX1, pWself2r, b2, nullptr, out, NN, 64, 256, nullptr);
    tgemm_nt<128, 64, 2, 4, true, false, false><<<dim3(1, MB), 256, SM_SMALL>>>(
        pM2, pWneigh2r, nullptr, nullptr, out, NN, 64, 256, nullptr);
}

// round 12
// speedup vs baseline: 2.2597x; 1.0767x over previous
#include <cuda_runtime.h>
#include <cstdint>

#define NN 30000
#define DMAXX 16

// ---------------- scratch (static device arrays; no cudaMalloc) -------------
__device__ __align__(16) float d_G1[(size_t)NN * 512];
__device__ __align__(16) float d_GB[(size_t)NN * 1024];
__device__ __align__(16) float d_H1p[(size_t)NN * 128];
__device__ __align__(16) float d_C1p[(size_t)NN * 128];
__device__ __align__(16) float d_M1[(size_t)NN * 128];
__device__ __align__(16) float d_X1[(size_t)NN * 256];
__device__ __align__(16) float d_G2[(size_t)NN * 1024];
__device__ __align__(16) float d_H2p[(size_t)NN * 256];
__device__ __align__(16) float d_C2p[(size_t)NN * 256];
__device__ __align__(16) float d_M2[(size_t)NN * 256];
__device__ __align__(16) float d_Fr[(size_t)NN * 128];
__device__ __align__(16) float d_Wih1r[512 * 128];
__device__ __align__(16) float d_Whh1r[512 * 128];
__device__ __align__(16) float d_Wih2r[1024 * 256];
__device__ __align__(16) float d_Whh2r[1024 * 256];
__device__ __align__(16) float d_Wfc1[256 * 256];   // [Wself1|Wneigh1] rounded
__device__ __align__(16) float d_Wfc2[64 * 512];    // [Wself2|Wneigh2] rounded
__device__ int d_perm[NN];
__device__ int d_hist[17];
__device__ int d_suffix[18];
__device__ int d_offset[17];

// ---------------- tf32 round helpers ----------------------------------------
__device__ __forceinline__ uint32_t f2tf32(float x) {
    uint32_t y;
    asm("cvt.rna.tf32.f32 %0, %1;" : "=r"(y) : "f"(x));
    return y;
}
__device__ __forceinline__ float rtf(float x) { return __uint_as_float(f2tf32(x)); }

__device__ __forceinline__ float4 rtf4(float4 v) {
    v.x = rtf(v.x); v.y = rtf(v.y); v.z = rtf(v.z); v.w = rtf(v.w);
    return v;
}

// fused rounding of feat + the 4 LSTM weight matrices (one launch)
#define R_FEAT 960000          // 30000*128/4
#define R_WIH1 (R_FEAT + 16384)
#define R_WHH1 (R_WIH1 + 16384)
#define R_WIH2 (R_WHH1 + 65536)
#define R_WHH2 (R_WIH2 + 65536)
__global__ void k_round_all(const float* __restrict__ feat,
                            const float* __restrict__ wih1, const float* __restrict__ whh1,
                            const float* __restrict__ wih2, const float* __restrict__ whh2) {
    int i = blockIdx.x * blockDim.x + threadIdx.x;
    if (i < R_FEAT)      ((float4*)d_Fr)[i]    = rtf4(((const float4*)feat)[i]);
    else if (i < R_WIH1) ((float4*)d_Wih1r)[i - R_FEAT] = rtf4(((const float4*)wih1)[i - R_FEAT]);
    else if (i < R_WHH1) ((float4*)d_Whh1r)[i - R_WIH1] = rtf4(((const float4*)whh1)[i - R_WIH1]);
    else if (i < R_WIH2) ((float4*)d_Wih2r)[i - R_WHH1] = rtf4(((const float4*)wih2)[i - R_WHH1]);
    else if (i < R_WHH2) ((float4*)d_Whh2r)[i - R_WIH2] = rtf4(((const float4*)whh2)[i - R_WIH2]);
}

// pack two K-major weight matrices side by side (rounded): out[r][0:k1]=a, [k1:k1+k2]=b
__global__ void k_pack2(const float* __restrict__ a, const float* __restrict__ b,
                        float* __restrict__ out, int rows, int k1, int k2) {
    int ktot = k1 + k2;
    int n4 = rows * ktot / 4;
    int i = blockIdx.x * blockDim.x + threadIdx.x;
    if (i >= n4) return;
    int r = i / (ktot / 4), c4 = (i % (ktot / 4)) * 4;
    float4 v = (c4 < k1) ? *(const float4*)&a[(size_t)r * k1 + c4]
                         : *(const float4*)&b[(size_t)r * k2 + (c4 - k1)];
    ((float4*)out)[i] = rtf4(v);
}

// ---------------- degree counting sort (descending) -------------------------
__global__ void k_hist_zero() { if (threadIdx.x < 17) d_hist[threadIdx.x] = 0; }
__global__ void k_hist(const int* __restrict__ deg) {
    int n = blockIdx.x * blockDim.x + threadIdx.x;
    if (n < NN) atomicAdd(&d_hist[deg[n]], 1);
}
__global__ void k_scan() {
    d_suffix[17] = 0;
    for (int dd = 16; dd >= 1; --dd) d_suffix[dd] = d_suffix[dd + 1] + d_hist[dd];
    d_suffix[0] = d_suffix[1];
    for (int dd = 1; dd <= 16; ++dd) d_offset[dd] = d_suffix[dd + 1];
}
__global__ void k_scatter(const int* __restrict__ deg) {
    int n = blockIdx.x * blockDim.x + threadIdx.x;
    if (n < NN) {
        int pos = atomicAdd(&d_offset[deg[n]], 1);
        d_perm[pos] = n;
    }
}

// ---------------- mma + cp.async helpers -------------------------------------
__device__ __forceinline__ void mma_tf32(float& c0, float& c1, float& c2, float& c3,
                                         uint32_t a0, uint32_t a1, uint32_t a2, uint32_t a3,
                                         uint32_t b0, uint32_t b1) {
    asm volatile(
        "mma.sync.aligned.m16n8k8.row.col.f32.tf32.tf32.f32 "
        "{%0,%1,%2,%3}, {%4,%5,%6,%7}, {%8,%9}, {%0,%1,%2,%3};"
        : "+f"(c0), "+f"(c1), "+f"(c2), "+f"(c3)
        : "r"(a0), "r"(a1), "r"(a2), "r"(a3), "r"(b0), "r"(b1));
}
__device__ __forceinline__ void cp_async16(uint32_t dst_smem, const void* src, int src_bytes) {
    asm volatile("cp.async.cg.shared.global [%0], [%1], 16, %2;"
                 :: "r"(dst_smem), "l"(src), "r"(src_bytes));
}
__device__ __forceinline__ void cp_commit() { asm volatile("cp.async.commit_group;"); }
__device__ __forceinline__ void cp_wait0() { asm volatile("cp.async.wait_group 0;"); }

// ---------------- tf32 GEMM: BK=32, cp.async 2-stage pipeline ----------------
// C[M,Nn] = [A|A2][M, K1+K2] @ W[Nn,K]^T (+bias) (relu) (round). A2 optional.
// Inputs pre-rounded to tf32 (rna); loads are raw 16B copies. K1 % 32 == 0.
template<int BM, int BN, int WARPS_M, int WARPS_N, bool RELU, bool ROUND>
__global__ __launch_bounds__(256, 2)
void tgemm_nt(const float* __restrict__ A, const float* __restrict__ A2, int K1,
              const float* __restrict__ W,
              const float* __restrict__ bias0, const float* __restrict__ bias1,
              float* __restrict__ C, int M, int Nn, int K,
              const int* rowsDev) {
    constexpr int BK = 32;
    constexpr int LDS_ = BK + 4;
    constexpr int WM = BM / WARPS_M;
    constexpr int WN = BN / WARPS_N;
    constexpr int MT = WM / 16;
    constexpr int NTT = WN / 8;
    constexpr int NTHR = WARPS_M * WARPS_N * 32;
    constexpr int AIT = BM * (BK / 4) / NTHR;
    constexpr int BIT = BN * (BK / 4) / NTHR;
    constexpr int ASTRIDE = BM * LDS_;
    constexpr int BSTRIDE = BN * LDS_;

    extern __shared__ uint32_t dynsmem[];
    uint32_t* AsBase = dynsmem;
    uint32_t* BsBase = dynsmem + 2 * ASTRIDE;
    const uint32_t sbase = (uint32_t)__cvta_generic_to_shared(dynsmem);
    const uint32_t sbaseB = sbase + 2 * ASTRIDE * 4;

    int rows = rowsDev ? *rowsDev : M;
    int rowBase = blockIdx.y * BM;
    if (rowBase >= rows) return;
    int colBase = blockIdx.x * BN;

    int tid = threadIdx.x;
    int wid = tid >> 5, lane = tid & 31;
    int wm = wid / WARPS_N, wn = wid % WARPS_N;
    int grp = lane >> 2, tg = lane & 3;

    float acc[MT][NTT][4];
#pragma unroll
    for (int i = 0; i < MT; i++)
#pragma unroll
        for (int j = 0; j < NTT; j++) {
            acc[i][j][0] = 0.f; acc[i][j][1] = 0.f; acc[i][j][2] = 0.f; acc[i][j][3] = 0.f;
        }

    const int ar = tid / (BK / 4);
    const int ac4 = (tid % (BK / 4)) * 4;
    constexpr int ARSTEP = NTHR / (BK / 4);
    const int K2 = K - K1;

    auto issue_tile = [&](int k0, int stg) {
        const float* srcA;
        int strA, c0;
        if (A2 && k0 >= K1) { srcA = A2; strA = K2; c0 = k0 - K1; }
        else { srcA = A; strA = K1; c0 = k0; }
#pragma unroll
        for (int u = 0; u < AIT; u++) {
            int r = ar + u * ARSTEP;
            int gr = rowBase + r;
            uint32_t dst = sbase + (uint32_t)(stg * ASTRIDE + r * LDS_ + ac4) * 4;
            cp_async16(dst, &srcA[(size_t)gr * strA + c0 + ac4], (gr < rows) ? 16 : 0);
        }
#pragma unroll
        for (int u = 0; u < BIT; u++) {
            int r = ar + u * ARSTEP;
            uint32_t dst = sbaseB + (uint32_t)(stg * BSTRIDE + r * LDS_ + ac4) * 4;
            cp_async16(dst, &W[(size_t)(colBase + r) * K + k0 + ac4], 16);
        }
        cp_commit();
    };

    issue_tile(0, 0);

    int stage = 0;
    for (int k0 = 0; k0 < K; k0 += BK, stage ^= 1) {
        cp_wait0();
        __syncthreads();
        int kn = k0 + BK;
        if (kn < K) issue_tile(kn, stage ^ 1);

        uint32_t* As = AsBase + stage * ASTRIDE;
        uint32_t* Bs = BsBase + stage * BSTRIDE;
#pragma unroll
        for (int kk = 0; kk < BK; kk += 8) {
            uint32_t af[MT][4];
#pragma unroll
            for (int i = 0; i < MT; i++) {
                int r0 = wm * WM + i * 16 + grp;
                int c = kk + tg;
                af[i][0] = As[r0 * LDS_ + c];
                af[i][1] = As[(r0 + 8) * LDS_ + c];
                af[i][2] = As[r0 * LDS_ + c + 4];
                af[i][3] = As[(r0 + 8) * LDS_ + c + 4];
            }
            uint32_t bf[NTT][2];
#pragma unroll
            for (int j = 0; j < NTT; j++) {
                int n0 = wn * WN + j * 8 + grp;
                bf[j][0] = Bs[n0 * LDS_ + kk + tg];
                bf[j][1] = Bs[n0 * LDS_ + kk + tg + 4];
            }
#pragma unroll
            for (int i = 0; i < MT; i++)
#pragma unroll
                for (int j = 0; j < NTT; j++)
                    mma_tf32(acc[i][j][0], acc[i][j][1], acc[i][j][2], acc[i][j][3],
                             af[i][0], af[i][1], af[i][2], af[i][3], bf[j][0], bf[j][1]);
        }
        __syncthreads();
    }

#pragma unroll
    for (int i = 0; i < MT; i++) {
#pragma unroll
        for (int j = 0; j < NTT; j++) {
            int gc = colBase + wn * WN + j * 8 + 2 * tg;
            float b0v = 0.f, b1v = 0.f;
            if (bias0) { b0v += bias0[gc]; b1v += bias0[gc + 1]; }
            if (bias1) { b0v += bias1[gc]; b1v += bias1[gc + 1]; }
            int gr0 = rowBase + wm * WM + i * 16 + grp;
            if (gr0 < rows) {
                float v0 = acc[i][j][0] + b0v, v1 = acc[i][j][1] + b1v;
                if (RELU) { v0 = fmaxf(v0, 0.f); v1 = fmaxf(v1, 0.f); }
                if (ROUND) { v0 = rtf(v0); v1 = rtf(v1); }
                *(float2*)&C[(size_t)gr0 * Nn + gc] = make_float2(v0, v1);
            }
            int gr1 = gr0 + 8;
            if (gr1 < rows) {
                float v0 = acc[i][j][2] + b0v, v1 = acc[i][j][3] + b1v;
                if (RELU) { v0 = fmaxf(v0, 0.f); v1 = fmaxf(v1, 0.f); }
                if (ROUND) { v0 = rtf(v0); v1 = rtf(v1); }
                *(float2*)&C[(size_t)gr1 * Nn + gc] = make_float2(v0, v1);
            }
        }
    }
}

// ---------------- fast activations (hardware MUFU.TANH) ----------------------
__device__ __forceinline__ float tanh_f(float x) {
    float y;
    asm("tanh.approx.f32 %0, %1;" : "=f"(y) : "f"(x));
    return y;
}
__device__ __forceinline__ float sigm_(float x) {
    return fmaf(tanh_f(0.5f * x), 0.5f, 0.5f);
}

// t = 0 step: gates come straight from G. C full precision; H stored rounded.
template<int H>
__global__ void lstm_step0(const float* __restrict__ G, const int* __restrict__ nbr,
                           float* __restrict__ Hp, float* __restrict__ Cp) {
    constexpr int TPN = H / 4;
    int cnt = d_suffix[1];
    int idx = blockIdx.x * blockDim.x + threadIdx.x;
    int p = idx / TPN;
    if (p >= cnt) return;
    int lane = idx % TPN;
    int node = d_perm[p];
    int nr = nbr[node * DMAXX];
    const float4* gx = (const float4*)&G[(size_t)nr * 4 * H];
    float4 xi = gx[lane], xg = gx[2 * TPN + lane], xo = gx[3 * TPN + lane];
    float4 c, h;
    c.x = sigm_(xi.x) * tanh_f(xg.x); h.x = rtf(sigm_(xo.x) * tanh_f(c.x));
    c.y = sigm_(xi.y) * tanh_f(xg.y); h.y = rtf(sigm_(xo.y) * tanh_f(c.y));
    c.z = sigm_(xi.z) * tanh_f(xg.z); h.z = rtf(sigm_(xo.z) * tanh_f(c.z));
    c.w = sigm_(xi.w) * tanh_f(xg.w); h.w = rtf(sigm_(xo.w) * tanh_f(c.w));
    ((float4*)&Cp[(size_t)p * H])[lane] = c;
    ((float4*)&Hp[(size_t)p * H])[lane] = h;
}

// layer 1: H=128; 32 threads/node. H stored rounded, C full precision.
__global__ void lstm_step1(const int* __restrict__ nbr, int t) {
    int cnt = d_suffix[t + 1];
    int idx = blockIdx.x * blockDim.x + threadIdx.x;
    int p = idx >> 5;
    if (p >= cnt) return;
    int lane = idx & 31;
    int node = d_perm[p];
    int nr = nbr[node * DMAXX + t];
    const float4* gb = (const float4*)&d_GB[(size_t)p * 512];
    const float4* gx = (const float4*)&d_G1[(size_t)nr * 512];
    float4 gi = gb[lane],       xi = gx[lane];
    float4 gf = gb[32 + lane],  xf = gx[32 + lane];
    float4 gg = gb[64 + lane],  xg = gx[64 + lane];
    float4 go = gb[96 + lane],  xo = gx[96 + lane];
    float4* cp = (float4*)&d_C1p[(size_t)p * 128];
    float4* hp = (float4*)&d_H1p[(size_t)p * 128];
    float4 c = cp[lane];
    float4 h;
    c.x = sigm_(gf.x + xf.x) * c.x + sigm_(gi.x + xi.x) * tanh_f(gg.x + xg.x); h.x = rtf(sigm_(go.x + xo.x) * tanh_f(c.x));
    c.y = sigm_(gf.y + xf.y) * c.y + sigm_(gi.y + xi.y) * tanh_f(gg.y + xg.y); h.y = rtf(sigm_(go.y + xo.y) * tanh_f(c.y));
    c.z = sigm_(gf.z + xf.z) * c.z + sigm_(gi.z + xi.z) * tanh_f(gg.z + xg.z); h.z = rtf(sigm_(go.z + xo.z) * tanh_f(c.z));
    c.w = sigm_(gf.w + xf.w) * c.w + sigm_(gi.w + xi.w) * tanh_f(gg.w + xg.w); h.w = rtf(sigm_(go.w + xo.w) * tanh_f(c.w));
    cp[lane] = c; hp[lane] = h;
}

// layer 2: H=256; 64 threads/node
__global__ void lstm_step2(const int* __restrict__ nbr, int t) {
    int cnt = d_suffix[t + 1];
    int idx = blockIdx.x * blockDim.x + threadIdx.x;
    int p = idx >> 6;
    if (p >= cnt) return;
    int lane = idx & 63;
    int node = d_perm[p];
    int nr = nbr[node * DMAXX + t];
    const float4* gb = (const float4*)&d_GB[(size_t)p * 1024];
    const float4* gx = (const float4*)&d_G2[(size_t)nr * 1024];
    float4 gi = gb[lane],        xi = gx[lane];
    float4 gf = gb[64 + lane],   xf = gx[64 + lane];
    float4 gg = gb[128 + lane],  xg = gx[128 + lane];
    float4 go = gb[192 + lane],  xo = gx[192 + lane];
    float4* cp = (float4*)&d_C2p[(size_t)p * 256];
    float4* hp = (float4*)&d_H2p[(size_t)p * 256];
    float4 c = cp[lane];
    float4 h;
    c.x = sigm_(gf.x + xf.x) * c.x + sigm_(gi.x + xi.x) * tanh_f(gg.x + xg.x); h.x = rtf(sigm_(go.x + xo.x) * tanh_f(c.x));
    c.y = sigm_(gf.y + xf.y) * c.y + sigm_(gi.y + xi.y) * tanh_f(gg.y + xg.y); h.y = rtf(sigm_(go.y + xo.y) * tanh_f(c.y));
    c.z = sigm_(gf.z + xf.z) * c.z + sigm_(gi.z + xi.z) * tanh_f(gg.z + xg.z); h.z = rtf(sigm_(go.z + xo.z) * tanh_f(c.z));
    c.w = sigm_(gf.w + xf.w) * c.w + sigm_(gi.w + xi.w) * tanh_f(gg.w + xg.w); h.w = rtf(sigm_(go.w + xo.w) * tanh_f(c.w));
    cp[lane] = c; hp[lane] = h;
}

// scatter permuted final hidden state back to natural node order
__global__ void k_scatter_h1() {
    int idx = blockIdx.x * blockDim.x + threadIdx.x;
    if (idx >= NN * 32) return;
    int p = idx >> 5, lane = idx & 31;
    int node = d_perm[p];
    ((float4*)d_M1)[node * 32 + lane] = ((const float4*)d_H1p)[p * 32 + lane];
}
__global__ void k_scatter_h2() {
    int idx = blockIdx.x * blockDim.x + threadIdx.x;
    if (idx >= NN * 64) return;
    int p = idx >> 6, lane = idx & 63;
    int node = d_perm[p];
    ((float4*)d_M2)[node * 64 + lane] = ((const float4*)d_H2p)[p * 64 + lane];
}

// ---------------- launch -----------------------------------------------------
extern "C" void kernel_launch(void* const* d_in, const int* in_sizes, int n_in,
                              void* d_out, int out_size) {
    const float* feat    = (const float*)d_in[0];
    const int*   nbr     = (const int*)  d_in[1];
    const int*   deg     = (const int*)  d_in[2];
    const float* Wih1    = (const float*)d_in[3];
    const float* Whh1    = (const float*)d_in[4];
    const float* bih1    = (const float*)d_in[5];
    const float* bhh1    = (const float*)d_in[6];
    const float* Wself1  = (const float*)d_in[7];
    const float* Wneigh1 = (const float*)d_in[8];
    const float* b1      = (const float*)d_in[9];
    const float* Wih2    = (const float*)d_in[10];
    const float* Whh2    = (const float*)d_in[11];
    const float* bih2    = (const float*)d_in[12];
    const float* bhh2    = (const float*)d_in[13];
    const float* Wself2  = (const float*)d_in[14];
    const float* Wneigh2 = (const float*)d_in[15];
    const float* b2      = (const float*)d_in[16];
    float* out = (float*)d_out;

    float *pG1, *pGB, *pH1, *pC1, *pM1, *pX1, *pG2, *pH2, *pC2, *pM2, *pFr;
    float *pWih1r, *pWhh1r, *pWih2r, *pWhh2r, *pWfc1, *pWfc2;
    int* pSuf;
    cudaGetSymbolAddress((void**)&pG1, d_G1);
    cudaGetSymbolAddress((void**)&pGB, d_GB);
    cudaGetSymbolAddress((void**)&pH1, d_H1p);
    cudaGetSymbolAddress((void**)&pC1, d_C1p);
    cudaGetSymbolAddress((void**)&pM1, d_M1);
    cudaGetSymbolAddress((void**)&pX1, d_X1);
    cudaGetSymbolAddress((void**)&pG2, d_G2);
    cudaGetSymbolAddress((void**)&pH2, d_H2p);
    cudaGetSymbolAddress((void**)&pC2, d_C2p);
    cudaGetSymbolAddress((void**)&pM2, d_M2);
    cudaGetSymbolAddress((void**)&pFr, d_Fr);
    cudaGetSymbolAddress((void**)&pWih1r, d_Wih1r);
    cudaGetSymbolAddress((void**)&pWhh1r, d_Whh1r);
    cudaGetSymbolAddress((void**)&pWih2r, d_Wih2r);
    cudaGetSymbolAddress((void**)&pWhh2r, d_Whh2r);
    cudaGetSymbolAddress((void**)&pWfc1, d_Wfc1);
    cudaGetSymbolAddress((void**)&pWfc2, d_Wfc2);
    cudaGetSymbolAddress((void**)&pSuf, d_suffix);

    const int SM_BIG = 2 * (128 + 128) * 36 * 4;    // 73728
    const int SM_SMALL = 2 * (128 + 64) * 36 * 4;   // 55296
    cudaFuncSetAttribute((const void*)tgemm_nt<128, 128, 2, 4, false, false>,
                         cudaFuncAttributeMaxDynamicSharedMemorySize, SM_BIG);
    cudaFuncSetAttribute((const void*)tgemm_nt<128, 128, 2, 4, true, true>,
                         cudaFuncAttributeMaxDynamicSharedMemorySize, SM_BIG);
    cudaFuncSetAttribute((const void*)tgemm_nt<128, 64, 2, 4, false, false>,
                         cudaFuncAttributeMaxDynamicSharedMemorySize, SM_SMALL);

    const int MB = (NN + 127) / 128;   // 235

    // pre-rounding: 3 launches instead of 9
    k_round_all<<<(R_WHH2 + 255) / 256, 256>>>(feat, Wih1, Whh1, Wih2, Whh2);
    k_pack2<<<(256 * 256 / 4 + 255) / 256, 256>>>(Wself1, Wneigh1, pWfc1, 256, 128, 128);
    k_pack2<<<(64 * 512 / 4 + 255) / 256, 256>>>(Wself2, Wneigh2, pWfc2, 64, 256, 256);

    k_hist_zero<<<1, 32>>>();
    k_hist<<<(NN + 255) / 256, 256>>>(deg);
    k_scan<<<1, 1>>>();
    k_scatter<<<(NN + 255) / 256, 256>>>(deg);

    // ---------------- layer 1 ----------------
    tgemm_nt<128, 128, 2, 4, false, false><<<dim3(4, MB), 256, SM_BIG>>>(
        pFr, nullptr, 128, pWih1r, bih1, bhh1, pG1, NN, 512, 128, nullptr);
    lstm_step0<128><<<(NN * 32 + 255) / 256, 256>>>(pG1, nbr, pH1, pC1);
    for (int t = 1; t < DMAXX; t++) {
        tgemm_nt<128, 128, 2, 4, false, false><<<dim3(4, MB), 256, SM_BIG>>>(
            pH1, nullptr, 128, pWhh1r, nullptr, nullptr, pGB, NN, 512, 128, pSuf + (t + 1));
        lstm_step1<<<(NN * 32 + 255) / 256, 256>>>(nbr, t);
    }
    k_scatter_h1<<<(NN * 32 + 255) / 256, 256>>>();
    // X1 = relu([feat|M1] @ Wfc1^T + b1), rounded (single merged FC GEMM)
    tgemm_nt<128, 128, 2, 4, true, true><<<dim3(2, MB), 256, SM_BIG>>>(
        pFr, pM1, 128, pWfc1, b1, nullptr, pX1, NN, 256, 256, nullptr);

    // ---------------- layer 2 ----------------
    tgemm_nt<128, 128, 2, 4, false, false><<<dim3(8, MB), 256, SM_BIG>>>(
        pX1, nullptr, 256, pWih2r, bih2, bhh2, pG2, NN, 1024, 256, nullptr);
    lstm_step0<256><<<(NN * 64 + 255) / 256, 256>>>(pG2, nbr, pH2, pC2);
    for (int t = 1; t < DMAXX; t++) {
        tgemm_nt<128, 128, 2, 4, false, false><<<dim3(8, MB), 256, SM_BIG>>>(
            pH2, nullptr, 256, pWhh2r, nullptr, nullptr, pGB, NN, 1024, 256, pSuf + (t + 1));
        lstm_step2<<<(NN * 64 + 255) / 256, 256>>>(nbr, t);
    }
    k_scatter_h2<<<(NN * 64 + 255) / 256, 256>>>();
    // out = [X1|M2] @ Wfc2^T + b2 (single merged FC GEMM)
    tgemm_nt<128, 64, 2, 4, false, false><<<dim3(1, MB), 256, SM_SMALL>>>(
        pX1, pM2, 256, pWfc2, b2, nullptr, out, NN, 64, 512, nullptr);
}

// round 13
// speedup vs baseline: 2.2991x; 1.0175x over previous
#include <cuda_runtime.h>
#include <cstdint>

#define NN 30000
#define DMAXX 16

// ---------------- scratch (static device arrays; no cudaMalloc) -------------
__device__ __align__(16) float d_G1[(size_t)NN * 512];
__device__ __align__(16) float d_GB[(size_t)NN * 1024];
__device__ __align__(16) float d_H1p[(size_t)NN * 128];
__device__ __align__(16) float d_C1p[(size_t)NN * 128];
__device__ __align__(16) float d_M1[(size_t)NN * 128];
__device__ __align__(16) float d_X1[(size_t)NN * 256];
__device__ __align__(16) float d_G2[(size_t)NN * 1024];
__device__ __align__(16) float d_H2p[(size_t)NN * 256];
__device__ __align__(16) float d_C2p[(size_t)NN * 256];
__device__ __align__(16) float d_M2[(size_t)NN * 256];
__device__ __align__(16) float d_Fr[(size_t)NN * 128];
__device__ __align__(16) float d_Wih1r[512 * 128];
__device__ __align__(16) float d_Whh1r[512 * 128];
__device__ __align__(16) float d_Wih2r[1024 * 256];
__device__ __align__(16) float d_Whh2r[1024 * 256];
__device__ __align__(16) float d_Wfc1[256 * 256];   // [Wself1|Wneigh1] rounded
__device__ __align__(16) float d_Wfc2[64 * 512];    // [Wself2|Wneigh2] rounded
__device__ int d_perm[NN];
__device__ int d_hist[17];
__device__ int d_suffix[18];
__device__ int d_offset[17];

// ---------------- tf32 round helpers ----------------------------------------
__device__ __forceinline__ uint32_t f2tf32(float x) {
    uint32_t y;
    asm("cvt.rna.tf32.f32 %0, %1;" : "=r"(y) : "f"(x));
    return y;
}
__device__ __forceinline__ float rtf(float x) { return __uint_as_float(f2tf32(x)); }

__device__ __forceinline__ float4 rtf4(float4 v) {
    v.x = rtf(v.x); v.y = rtf(v.y); v.z = rtf(v.z); v.w = rtf(v.w);
    return v;
}

// fused rounding of feat + the 4 LSTM weight matrices (one launch)
#define R_FEAT 960000          // 30000*128/4
#define R_WIH1 (R_FEAT + 16384)
#define R_WHH1 (R_WIH1 + 16384)
#define R_WIH2 (R_WHH1 + 65536)
#define R_WHH2 (R_WIH2 + 65536)
__global__ void k_round_all(const float* __restrict__ feat,
                            const float* __restrict__ wih1, const float* __restrict__ whh1,
                            const float* __restrict__ wih2, const float* __restrict__ whh2) {
    int i = blockIdx.x * blockDim.x + threadIdx.x;
    if (i < R_FEAT)      ((float4*)d_Fr)[i]    = rtf4(((const float4*)feat)[i]);
    else if (i < R_WIH1) ((float4*)d_Wih1r)[i - R_FEAT] = rtf4(((const float4*)wih1)[i - R_FEAT]);
    else if (i < R_WHH1) ((float4*)d_Whh1r)[i - R_WIH1] = rtf4(((const float4*)whh1)[i - R_WIH1]);
    else if (i < R_WIH2) ((float4*)d_Wih2r)[i - R_WHH1] = rtf4(((const float4*)wih2)[i - R_WHH1]);
    else if (i < R_WHH2) ((float4*)d_Whh2r)[i - R_WIH2] = rtf4(((const float4*)whh2)[i - R_WIH2]);
}

// pack two K-major weight matrices side by side (rounded)
__global__ void k_pack2(const float* __restrict__ a, const float* __restrict__ b,
                        float* __restrict__ out, int rows, int k1, int k2) {
    int ktot = k1 + k2;
    int n4 = rows * ktot / 4;
    int i = blockIdx.x * blockDim.x + threadIdx.x;
    if (i >= n4) return;
    int r = i / (ktot / 4), c4 = (i % (ktot / 4)) * 4;
    float4 v = (c4 < k1) ? *(const float4*)&a[(size_t)r * k1 + c4]
                         : *(const float4*)&b[(size_t)r * k2 + (c4 - k1)];
    ((float4*)out)[i] = rtf4(v);
}

// ---------------- degree counting sort (descending) -------------------------
__global__ void k_hist_zero() { if (threadIdx.x < 17) d_hist[threadIdx.x] = 0; }
__global__ void k_hist(const int* __restrict__ deg) {
    int n = blockIdx.x * blockDim.x + threadIdx.x;
    if (n < NN) atomicAdd(&d_hist[deg[n]], 1);
}
__global__ void k_scan() {
    d_suffix[17] = 0;
    for (int dd = 16; dd >= 1; --dd) d_suffix[dd] = d_suffix[dd + 1] + d_hist[dd];
    d_suffix[0] = d_suffix[1];
    for (int dd = 1; dd <= 16; ++dd) d_offset[dd] = d_suffix[dd + 1];
}
__global__ void k_scatter(const int* __restrict__ deg) {
    int n = blockIdx.x * blockDim.x + threadIdx.x;
    if (n < NN) {
        int pos = atomicAdd(&d_offset[deg[n]], 1);
        d_perm[pos] = n;
    }
}

// ---------------- mma + cp.async helpers -------------------------------------
__device__ __forceinline__ void mma_tf32(float& c0, float& c1, float& c2, float& c3,
                                         uint32_t a0, uint32_t a1, uint32_t a2, uint32_t a3,
                                         uint32_t b0, uint32_t b1) {
    asm volatile(
        "mma.sync.aligned.m16n8k8.row.col.f32.tf32.tf32.f32 "
        "{%0,%1,%2,%3}, {%4,%5,%6,%7}, {%8,%9}, {%0,%1,%2,%3};"
        : "+f"(c0), "+f"(c1), "+f"(c2), "+f"(c3)
        : "r"(a0), "r"(a1), "r"(a2), "r"(a3), "r"(b0), "r"(b1));
}
__device__ __forceinline__ void cp_async16(uint32_t dst_smem, const void* src, int src_bytes) {
    asm volatile("cp.async.cg.shared.global [%0], [%1], 16, %2;"
                 :: "r"(dst_smem), "l"(src), "r"(src_bytes));
}
__device__ __forceinline__ void cp_commit() { asm volatile("cp.async.commit_group;"); }
__device__ __forceinline__ void cp_wait0() { asm volatile("cp.async.wait_group 0;"); }
__device__ __forceinline__ void cp_wait1() { asm volatile("cp.async.wait_group 1;"); }

// ---------------- tf32 GEMM: BK=32, cp.async 3-stage pipeline ----------------
// C[M,Nn] = [A|A2][M, K1+K2] @ W[Nn,K]^T (+bias) (relu) (round). A2 optional.
// Inputs pre-rounded to tf32 (rna); loads are raw 16B copies. K1 % 32 == 0.
// 3 stages, 2 tiles in flight, ONE __syncthreads per tile.
template<int BM, int BN, int WARPS_M, int WARPS_N, bool RELU, bool ROUND>
__global__ __launch_bounds__(256, 2)
void tgemm_nt(const float* __restrict__ A, const float* __restrict__ A2, int K1,
              const float* __restrict__ W,
              const float* __restrict__ bias0, const float* __restrict__ bias1,
              float* __restrict__ C, int M, int Nn, int K,
              const int* rowsDev) {
    constexpr int BK = 32;
    constexpr int LDS_ = BK + 4;
    constexpr int STAGES = 3;
    constexpr int WM = BM / WARPS_M;
    constexpr int WN = BN / WARPS_N;
    constexpr int MT = WM / 16;
    constexpr int NTT = WN / 8;
    constexpr int NTHR = WARPS_M * WARPS_N * 32;
    constexpr int AIT = BM * (BK / 4) / NTHR;
    constexpr int BIT = BN * (BK / 4) / NTHR;
    constexpr int ASTRIDE = BM * LDS_;
    constexpr int BSTRIDE = BN * LDS_;

    extern __shared__ uint32_t dynsmem[];
    uint32_t* AsBase = dynsmem;
    uint32_t* BsBase = dynsmem + STAGES * ASTRIDE;
    const uint32_t sbase = (uint32_t)__cvta_generic_to_shared(dynsmem);
    const uint32_t sbaseB = sbase + STAGES * ASTRIDE * 4;

    int rows = rowsDev ? *rowsDev : M;
    int rowBase = blockIdx.y * BM;
    if (rowBase >= rows) return;
    int colBase = blockIdx.x * BN;

    int tid = threadIdx.x;
    int wid = tid >> 5, lane = tid & 31;
    int wm = wid / WARPS_N, wn = wid % WARPS_N;
    int grp = lane >> 2, tg = lane & 3;

    float acc[MT][NTT][4];
#pragma unroll
    for (int i = 0; i < MT; i++)
#pragma unroll
        for (int j = 0; j < NTT; j++) {
            acc[i][j][0] = 0.f; acc[i][j][1] = 0.f; acc[i][j][2] = 0.f; acc[i][j][3] = 0.f;
        }

    const int ar = tid / (BK / 4);
    const int ac4 = (tid % (BK / 4)) * 4;
    constexpr int ARSTEP = NTHR / (BK / 4);
    const int K2 = K - K1;

    auto issue_tile = [&](int k0, int stg) {
        const float* srcA;
        int strA, c0;
        if (A2 && k0 >= K1) { srcA = A2; strA = K2; c0 = k0 - K1; }
        else { srcA = A; strA = K1; c0 = k0; }
#pragma unroll
        for (int u = 0; u < AIT; u++) {
            int r = ar + u * ARSTEP;
            int gr = rowBase + r;
            uint32_t dst = sbase + (uint32_t)(stg * ASTRIDE + r * LDS_ + ac4) * 4;
            cp_async16(dst, &srcA[(size_t)gr * strA + c0 + ac4], (gr < rows) ? 16 : 0);
        }
#pragma unroll
        for (int u = 0; u < BIT; u++) {
            int r = ar + u * ARSTEP;
            uint32_t dst = sbaseB + (uint32_t)(stg * BSTRIDE + r * LDS_ + ac4) * 4;
            cp_async16(dst, &W[(size_t)(colBase + r) * K + k0 + ac4], 16);
        }
        cp_commit();
    };

    // prologue: two tiles in flight
    issue_tile(0, 0);
    if (BK < K) issue_tile(BK, 1);

    int stage = 0;
    for (int k0 = 0; k0 < K; k0 += BK) {
        // wait for tile k0: if another tile is still in flight behind it, allow 1 outstanding
        if (k0 + BK < K) cp_wait1(); else cp_wait0();
        __syncthreads();   // tile `stage` visible to all warps; also proves compute of
                           // tile k0-1 done by all warps -> stage (k0+2)%3 reusable

        int kn = k0 + 2 * BK;
        if (kn < K) issue_tile(kn, (stage + 2) % STAGES);

        uint32_t* As = AsBase + stage * ASTRIDE;
        uint32_t* Bs = BsBase + stage * BSTRIDE;
#pragma unroll
        for (int kk = 0; kk < BK; kk += 8) {
            uint32_t af[MT][4];
#pragma unroll
            for (int i = 0; i < MT; i++) {
                int r0 = wm * WM + i * 16 + grp;
                int c = kk + tg;
                af[i][0] = As[r0 * LDS_ + c];
                af[i][1] = As[(r0 + 8) * LDS_ + c];
                af[i][2] = As[r0 * LDS_ + c + 4];
                af[i][3] = As[(r0 + 8) * LDS_ + c + 4];
            }
            uint32_t bf[NTT][2];
#pragma unroll
            for (int j = 0; j < NTT; j++) {
                int n0 = wn * WN + j * 8 + grp;
                bf[j][0] = Bs[n0 * LDS_ + kk + tg];
                bf[j][1] = Bs[n0 * LDS_ + kk + tg + 4];
            }
#pragma unroll
            for (int i = 0; i < MT; i++)
#pragma unroll
                for (int j = 0; j < NTT; j++)
                    mma_tf32(acc[i][j][0], acc[i][j][1], acc[i][j][2], acc[i][j][3],
                             af[i][0], af[i][1], af[i][2], af[i][3], bf[j][0], bf[j][1]);
        }
        stage = (stage + 1) % STAGES;
    }

#pragma unroll
    for (int i = 0; i < MT; i++) {
#pragma unroll
        for (int j = 0; j < NTT; j++) {
            int gc = colBase + wn * WN + j * 8 + 2 * tg;
            float b0v = 0.f, b1v = 0.f;
            if (bias0) { b0v += bias0[gc]; b1v += bias0[gc + 1]; }
            if (bias1) { b0v += bias1[gc]; b1v += bias1[gc + 1]; }
            int gr0 = rowBase + wm * WM + i * 16 + grp;
            if (gr0 < rows) {
                float v0 = acc[i][j][0] + b0v, v1 = acc[i][j][1] + b1v;
                if (RELU) { v0 = fmaxf(v0, 0.f); v1 = fmaxf(v1, 0.f); }
                if (ROUND) { v0 = rtf(v0); v1 = rtf(v1); }
                *(float2*)&C[(size_t)gr0 * Nn + gc] = make_float2(v0, v1);
            }
            int gr1 = gr0 + 8;
            if (gr1 < rows) {
                float v0 = acc[i][j][2] + b0v, v1 = acc[i][j][3] + b1v;
                if (RELU) { v0 = fmaxf(v0, 0.f); v1 = fmaxf(v1, 0.f); }
                if (ROUND) { v0 = rtf(v0); v1 = rtf(v1); }
                *(float2*)&C[(size_t)gr1 * Nn + gc] = make_float2(v0, v1);
            }
        }
    }
}

// ---------------- fast activations (hardware MUFU.TANH) ----------------------
__device__ __forceinline__ float tanh_f(float x) {
    float y;
    asm("tanh.approx.f32 %0, %1;" : "=f"(y) : "f"(x));
    return y;
}
__device__ __forceinline__ float sigm_(float x) {
    return fmaf(tanh_f(0.5f * x), 0.5f, 0.5f);
}

// t = 0 step: gates come straight from G. C full precision; H stored rounded.
template<int H>
__global__ void lstm_step0(const float* __restrict__ G, const int* __restrict__ nbr,
                           float* __restrict__ Hp, float* __restrict__ Cp) {
    constexpr int TPN = H / 4;
    int cnt = d_suffix[1];
    int idx = blockIdx.x * blockDim.x + threadIdx.x;
    int p = idx / TPN;
    if (p >= cnt) return;
    int lane = idx % TPN;
    int node = d_perm[p];
    int nr = nbr[node * DMAXX];
    const float4* gx = (const float4*)&G[(size_t)nr * 4 * H];
    float4 xi = gx[lane], xg = gx[2 * TPN + lane], xo = gx[3 * TPN + lane];
    float4 c, h;
    c.x = sigm_(xi.x) * tanh_f(xg.x); h.x = rtf(sigm_(xo.x) * tanh_f(c.x));
    c.y = sigm_(xi.y) * tanh_f(xg.y); h.y = rtf(sigm_(xo.y) * tanh_f(c.y));
    c.z = sigm_(xi.z) * tanh_f(xg.z); h.z = rtf(sigm_(xo.z) * tanh_f(c.z));
    c.w = sigm_(xi.w) * tanh_f(xg.w); h.w = rtf(sigm_(xo.w) * tanh_f(c.w));
    ((float4*)&Cp[(size_t)p * H])[lane] = c;
    ((float4*)&Hp[(size_t)p * H])[lane] = h;
}

// layer 1: H=128; 32 threads/node. H stored rounded, C full precision.
__global__ void lstm_step1(const int* __restrict__ nbr, int t) {
    int cnt = d_suffix[t + 1];
    int idx = blockIdx.x * blockDim.x + threadIdx.x;
    int p = idx >> 5;
    if (p >= cnt) return;
    int lane = idx & 31;
    int node = d_perm[p];
    int nr = nbr[node * DMAXX + t];
    const float4* gb = (const float4*)&d_GB[(size_t)p * 512];
    const float4* gx = (const float4*)&d_G1[(size_t)nr * 512];
    float4 gi = gb[lane],       xi = gx[lane];
    float4 gf = gb[32 + lane],  xf = gx[32 + lane];
    float4 gg = gb[64 + lane],  xg = gx[64 + lane];
    float4 go = gb[96 + lane],  xo = gx[96 + lane];
    float4* cp = (float4*)&d_C1p[(size_t)p * 128];
    float4* hp = (float4*)&d_H1p[(size_t)p * 128];
    float4 c = cp[lane];
    float4 h;
    c.x = sigm_(gf.x + xf.x) * c.x + sigm_(gi.x + xi.x) * tanh_f(gg.x + xg.x); h.x = rtf(sigm_(go.x + xo.x) * tanh_f(c.x));
    c.y = sigm_(gf.y + xf.y) * c.y + sigm_(gi.y + xi.y) * tanh_f(gg.y + xg.y); h.y = rtf(sigm_(go.y + xo.y) * tanh_f(c.y));
    c.z = sigm_(gf.z + xf.z) * c.z + sigm_(gi.z + xi.z) * tanh_f(gg.z + xg.z); h.z = rtf(sigm_(go.z + xo.z) * tanh_f(c.z));
    c.w = sigm_(gf.w + xf.w) * c.w + sigm_(gi.w + xi.w) * tanh_f(gg.w + xg.w); h.w = rtf(sigm_(go.w + xo.w) * tanh_f(c.w));
    cp[lane] = c; hp[lane] = h;
}

// layer 2: H=256; 64 threads/node
__global__ void lstm_step2(const int* __restrict__ nbr, int t) {
    int cnt = d_suffix[t + 1];
    int idx = blockIdx.x * blockDim.x + threadIdx.x;
    int p = idx >> 6;
    if (p >= cnt) return;
    int lane = idx & 63;
    int node = d_perm[p];
    int nr = nbr[node * DMAXX + t];
    const float4* gb = (const float4*)&d_GB[(size_t)p * 1024];
    const float4* gx = (const float4*)&d_G2[(size_t)nr * 1024];
    float4 gi = gb[lane],        xi = gx[lane];
    float4 gf = gb[64 + lane],   xf = gx[64 + lane];
    float4 gg = gb[128 + lane],  xg = gx[128 + lane];
    float4 go = gb[192 + lane],  xo = gx[192 + lane];
    float4* cp = (float4*)&d_C2p[(size_t)p * 256];
    float4* hp = (float4*)&d_H2p[(size_t)p * 256];
    float4 c = cp[lane];
    float4 h;
    c.x = sigm_(gf.x + xf.x) * c.x + sigm_(gi.x + xi.x) * tanh_f(gg.x + xg.x); h.x = rtf(sigm_(go.x + xo.x) * tanh_f(c.x));
    c.y = sigm_(gf.y + xf.y) * c.y + sigm_(gi.y + xi.y) * tanh_f(gg.y + xg.y); h.y = rtf(sigm_(go.y + xo.y) * tanh_f(c.y));
    c.z = sigm_(gf.z + xf.z) * c.z + sigm_(gi.z + xi.z) * tanh_f(gg.z + xg.z); h.z = rtf(sigm_(go.z + xo.z) * tanh_f(c.z));
    c.w = sigm_(gf.w + xf.w) * c.w + sigm_(gi.w + xi.w) * tanh_f(gg.w + xg.w); h.w = rtf(sigm_(go.w + xo.w) * tanh_f(c.w));
    cp[lane] = c; hp[lane] = h;
}

// scatter permuted final hidden state back to natural node order
__global__ void k_scatter_h1() {
    int idx = blockIdx.x * blockDim.x + threadIdx.x;
    if (idx >= NN * 32) return;
    int p = idx >> 5, lane = idx & 31;
    int node = d_perm[p];
    ((float4*)d_M1)[node * 32 + lane] = ((const float4*)d_H1p)[p * 32 + lane];
}
__global__ void k_scatter_h2() {
    int idx = blockIdx.x * blockDim.x + threadIdx.x;
    if (idx >= NN * 64) return;
    int p = idx >> 6, lane = idx & 63;
    int node = d_perm[p];
    ((float4*)d_M2)[node * 64 + lane] = ((const float4*)d_H2p)[p * 64 + lane];
}

// ---------------- launch -----------------------------------------------------
extern "C" void kernel_launch(void* const* d_in, const int* in_sizes, int n_in,
                              void* d_out, int out_size) {
    const float* feat    = (const float*)d_in[0];
    const int*   nbr     = (const int*)  d_in[1];
    const int*   deg     = (const int*)  d_in[2];
    const float* Wih1    = (const float*)d_in[3];
    const float* Whh1    = (const float*)d_in[4];
    const float* bih1    = (const float*)d_in[5];
    const float* bhh1    = (const float*)d_in[6];
    const float* Wself1  = (const float*)d_in[7];
    const float* Wneigh1 = (const float*)d_in[8];
    const float* b1      = (const float*)d_in[9];
    const float* Wih2    = (const float*)d_in[10];
    const float* Whh2    = (const float*)d_in[11];
    const float* bih2    = (const float*)d_in[12];
    const float* bhh2    = (const float*)d_in[13];
    const float* Wself2  = (const float*)d_in[14];
    const float* Wneigh2 = (const float*)d_in[15];
    const float* b2      = (const float*)d_in[16];
    float* out = (float*)d_out;

    float *pG1, *pGB, *pH1, *pC1, *pM1, *pX1, *pG2, *pH2, *pC2, *pM2, *pFr;
    float *pWih1r, *pWhh1r, *pWih2r, *pWhh2r, *pWfc1, *pWfc2;
    int* pSuf;
    cudaGetSymbolAddress((void**)&pG1, d_G1);
    cudaGetSymbolAddress((void**)&pGB, d_GB);
    cudaGetSymbolAddress((void**)&pH1, d_H1p);
    cudaGetSymbolAddress((void**)&pC1, d_C1p);
    cudaGetSymbolAddress((void**)&pM1, d_M1);
    cudaGetSymbolAddress((void**)&pX1, d_X1);
    cudaGetSymbolAddress((void**)&pG2, d_G2);
    cudaGetSymbolAddress((void**)&pH2, d_H2p);
    cudaGetSymbolAddress((void**)&pC2, d_C2p);
    cudaGetSymbolAddress((void**)&pM2, d_M2);
    cudaGetSymbolAddress((void**)&pFr, d_Fr);
    cudaGetSymbolAddress((void**)&pWih1r, d_Wih1r);
    cudaGetSymbolAddress((void**)&pWhh1r, d_Whh1r);
    cudaGetSymbolAddress((void**)&pWih2r, d_Wih2r);
    cudaGetSymbolAddress((void**)&pWhh2r, d_Whh2r);
    cudaGetSymbolAddress((void**)&pWfc1, d_Wfc1);
    cudaGetSymbolAddress((void**)&pWfc2, d_Wfc2);
    cudaGetSymbolAddress((void**)&pSuf, d_suffix);

    const int SM_BIG = 3 * (128 + 128) * 36 * 4;    // 110592
    const int SM_SMALL = 3 * (128 + 64) * 36 * 4;   // 82944
    cudaFuncSetAttribute((const void*)tgemm_nt<128, 128, 2, 4, false, false>,
                         cudaFuncAttributeMaxDynamicSharedMemorySize, SM_BIG);
    cudaFuncSetAttribute((const void*)tgemm_nt<128, 128, 2, 4, true, true>,
                         cudaFuncAttributeMaxDynamicSharedMemorySize, SM_BIG);
    cudaFuncSetAttribute((const void*)tgemm_nt<128, 64, 2, 4, false, false>,
                         cudaFuncAttributeMaxDynamicSharedMemorySize, SM_SMALL);

    const int MB = (NN + 127) / 128;   // 235

    // pre-rounding: 3 launches
    k_round_all<<<(R_WHH2 + 255) / 256, 256>>>(feat, Wih1, Whh1, Wih2, Whh2);
    k_pack2<<<(256 * 256 / 4 + 255) / 256, 256>>>(Wself1, Wneigh1, pWfc1, 256, 128, 128);
    k_pack2<<<(64 * 512 / 4 + 255) / 256, 256>>>(Wself2, Wneigh2, pWfc2, 64, 256, 256);

    k_hist_zero<<<1, 32>>>();
    k_hist<<<(NN + 255) / 256, 256>>>(deg);
    k_scan<<<1, 1>>>();
    k_scatter<<<(NN + 255) / 256, 256>>>(deg);

    // ---------------- layer 1 ----------------
    tgemm_nt<128, 128, 2, 4, false, false><<<dim3(4, MB), 256, SM_BIG>>>(
        pFr, nullptr, 128, pWih1r, bih1, bhh1, pG1, NN, 512, 128, nullptr);
    lstm_step0<128><<<(NN * 32 + 255) / 256, 256>>>(pG1, nbr, pH1, pC1);
    for (int t = 1; t < DMAXX; t++) {
        tgemm_nt<128, 128, 2, 4, false, false><<<dim3(4, MB), 256, SM_BIG>>>(
            pH1, nullptr, 128, pWhh1r, nullptr, nullptr, pGB, NN, 512, 128, pSuf + (t + 1));
        lstm_step1<<<(NN * 32 + 255) / 256, 256>>>(nbr, t);
    }
    k_scatter_h1<<<(NN * 32 + 255) / 256, 256>>>();
    // X1 = relu([feat|M1] @ Wfc1^T + b1), rounded (single merged FC GEMM)
    tgemm_nt<128, 128, 2, 4, true, true><<<dim3(2, MB), 256, SM_BIG>>>(
        pFr, pM1, 128, pWfc1, b1, nullptr, pX1, NN, 256, 256, nullptr);

    // ---------------- layer 2 ----------------
    tgemm_nt<128, 128, 2, 4, false, false><<<dim3(8, MB), 256, SM_BIG>>>(
        pX1, nullptr, 256, pWih2r, bih2, bhh2, pG2, NN, 1024, 256, nullptr);
    lstm_step0<256><<<(NN * 64 + 255) / 256, 256>>>(pG2, nbr, pH2, pC2);
    for (int t = 1; t < DMAXX; t++) {
        tgemm_nt<128, 128, 2, 4, false, false><<<dim3(8, MB), 256, SM_BIG>>>(
            pX1 /*unused A2*/ == nullptr ? pH2 : pH2, nullptr, 256, pWhh2r, nullptr, nullptr, pGB, NN, 1024, 256, pSuf + (t + 1));
        lstm_step2<<<(NN * 64 + 255) / 256, 256>>>(nbr, t);
    }
    k_scatter_h2<<<(NN * 64 + 255) / 256, 256>>>();
    // out = [X1|M2] @ Wfc2^T + b2 (single merged FC GEMM)
    tgemm_nt<128, 64, 2, 4, false, false><<<dim3(1, MB), 256, SM_SMALL>>>(
        pX1, pM2, 256, pWfc2, b2, nullptr, out, NN, 64, 512, nullptr);
}